// round 15
// baseline (speedup 1.0000x reference)
#include <cuda_runtime.h>
#include <cuda_bf16.h>
#include <math.h>
#include <stdint.h>

#define BB 2
#define TT 4096
#define DD 1024
#define LL 2
#define HH 16
#define FF 4096
#define KK 2048
#define DHD 64
#define MROWS (BB*KK)   // 4096 (batch folded into M)

// ---------------- scratch (static device globals; no allocations) ----------------
__device__ float g_logits[BB*TT];
__device__ int   g_idx[BB*KK];
__device__ int   g_pos[BB*TT];     // token -> k-position (or -1)
__device__ float g_gate[BB*KK];
__device__ float g_h[BB*KK*DD];
__device__ __nv_bfloat16 g_a[BB*KK*DD];
__device__ float g_qkv[BB*KK*3*DD];
__device__ __nv_bfloat16 g_attn[BB*KK*DD];
__device__ __nv_bfloat16 g_ffn[(size_t)BB*KK*FF];

// transposed ([N][K] k-contiguous) bf16 weights
#define WT_QKV 0
#define WT_O   (LL*DD*3*DD)
#define WT_W1  (WT_O + LL*DD*DD)
#define WT_W2  (WT_W1 + LL*DD*FF)
#define WT_TOT (WT_W2 + LL*FF*DD)
__device__ __nv_bfloat16 g_wt[WT_TOT];

// ---------------- helpers ----------------
__device__ __forceinline__ uint32_t smem_u32(const void* p) {
    uint32_t a;
    asm("{ .reg .u64 t; cvta.to.shared.u64 t, %1; cvt.u32.u64 %0, t; }" : "=r"(a) : "l"(p));
    return a;
}
__device__ __forceinline__ float tf32rn(float x) {
    uint32_t u;
    asm("cvt.rna.tf32.f32 %0, %1;" : "=r"(u) : "f"(x));
    return __uint_as_float(u);
}
__device__ __forceinline__ void cpasync16(uint32_t dst, const void* src) {
    asm volatile("cp.async.cg.shared.global [%0], [%1], 16;" :: "r"(dst), "l"(src) : "memory");
}
__device__ __forceinline__ void cp_commit() {
    asm volatile("cp.async.commit_group;" ::: "memory");
}
__device__ __forceinline__ void mbar_init(uint32_t a, uint32_t cnt) {
    asm volatile("mbarrier.init.shared.b64 [%0], %1;" :: "r"(a), "r"(cnt) : "memory");
}
__device__ __forceinline__ void mbar_arrive(uint32_t a) {
    asm volatile("mbarrier.arrive.shared.b64 _, [%0];" :: "r"(a) : "memory");
}
__device__ __forceinline__ void mbar_wait(uint32_t a, uint32_t parity) {
    asm volatile(
        "{\n\t.reg .pred P;\n\tWL%=:\n\t"
        "mbarrier.try_wait.parity.acquire.cta.shared::cta.b64 P, [%0], %1;\n\t"
        "@P bra WD%=;\n\tbra WL%=;\n\tWD%=:\n\t}"
        :: "r"(a), "r"(parity) : "memory");
}
__device__ __forceinline__ void cpasync_arrive_noinc(uint32_t mbar) {
    asm volatile("cp.async.mbarrier.arrive.noinc.shared.b64 [%0];" :: "r"(mbar) : "memory");
}
__device__ __forceinline__ void ldsm4(uint32_t& r0, uint32_t& r1, uint32_t& r2, uint32_t& r3,
                                      uint32_t addr) {
    asm volatile("ldmatrix.sync.aligned.m8n8.x4.shared.b16 {%0,%1,%2,%3}, [%4];"
        : "=r"(r0), "=r"(r1), "=r"(r2), "=r"(r3) : "r"(addr));
}
__device__ __forceinline__ void mma16(float* d, const uint32_t* a, const uint32_t* b) {
    asm volatile("mma.sync.aligned.m16n8k16.row.col.f32.bf16.bf16.f32 "
        "{%0,%1,%2,%3}, {%4,%5,%6,%7}, {%8,%9}, {%0,%1,%2,%3};"
        : "+f"(d[0]), "+f"(d[1]), "+f"(d[2]), "+f"(d[3])
        : "r"(a[0]), "r"(a[1]), "r"(a[2]), "r"(a[3]), "r"(b[0]), "r"(b[1]));
}
__device__ __forceinline__ void mma8(float* d, const float* a, const float* b) {
    asm volatile("mma.sync.aligned.m16n8k8.row.col.f32.tf32.tf32.f32 "
        "{%0,%1,%2,%3}, {%4,%5,%6,%7}, {%8,%9}, {%0,%1,%2,%3};"
        : "+f"(d[0]), "+f"(d[1]), "+f"(d[2]), "+f"(d[3])
        : "r"(__float_as_uint(a[0])), "r"(__float_as_uint(a[1])),
          "r"(__float_as_uint(a[2])), "r"(__float_as_uint(a[3])),
          "r"(__float_as_uint(b[0])), "r"(__float_as_uint(b[1])));
}

__device__ __forceinline__ float gelu_f(float x) {
    float x3 = x * x * x;
    float t = tanhf(0.7978845608028654f * (x + 0.044715f * x3));
    return 0.5f * x * (1.f + t);
}

// ---------------- warp-specialized bf16 m16n8k16 GEMM ----------------
// C = A(M x Kd) @ Wt^T + bias.  A: [M][Kd] bf16; Wt: [Ntot][Kd] bf16.
// CTA tile 128x128. 8 consumer warps (32x64 tiles, staggered B frags) + 1 producer warp.
// 3-stage cp.async ring (K-chunk 64), mbarrier full/done; no CTA barrier in mainloop.
#define MT 128
#define NTB 128
#define KCHB 64                          // bf16 k elements per stage
#define TSTB 144                         // row stride in BYTES (72 bf16)
#define STG_BYTES ((MT+NTB)*TSTB)        // 36864
#define NSTG 3
#define GEMM_SMEM (NSTG*STG_BYTES)       // 110592 -> 2 CTAs/SM
#define GEMM_THREADS 288                 // 256 consumer + 32 producer

// EPI: 0 = bias, 1 = bias+gelu -> bf16 out, 2 = bias+residual (fp32), 3 = bias (fp32)
template <int EPI>
__global__ __launch_bounds__(GEMM_THREADS, 2) void mma_gemm(
    const __nv_bfloat16* __restrict__ A, const __nv_bfloat16* __restrict__ Wt,
    const float* __restrict__ bias, const float* __restrict__ res,
    float* __restrict__ C, int Kd, int Ntot)
{
    extern __shared__ __align__(16) char smc[];
    __shared__ __align__(8) uint64_t mbars[2*NSTG];   // full[s], done[s]
    uint32_t sbase = smem_u32(smc);
    uint32_t barb  = smem_u32(mbars);

    int tid = threadIdx.x;
    int bn = blockIdx.x, bm = blockIdx.y;
    int wid = tid >> 5, lane = tid & 31;
    int nk = Kd / KCHB;

    if (tid == 0) {
        for (int s = 0; s < NSTG; s++) {
            mbar_init(barb + 16*s, 32);      // full: 32 producer arrivals (noinc)
            mbar_init(barb + 16*s + 8, 8);   // done: 8 consumer-warp arrivals
        }
    }
    __syncthreads();

    if (wid == 8) {
        // ---- producer warp: fills stages (256 rows x 128 B) ----
        const __nv_bfloat16* Ag = A + (size_t)(bm*MT) * Kd;
        const __nv_bfloat16* Bg = Wt + (size_t)(bn*NTB) * Kd;
        int s = 0, ph = 1;
        for (int kt = 0; kt < nk; kt++) {
            mbar_wait(barb + 16*s + 8, ph);
            uint32_t stb = sbase + (uint32_t)(s*STG_BYTES);
            const __nv_bfloat16* Ak = Ag + kt*KCHB;
            const __nv_bfloat16* Bk = Bg + kt*KCHB;
#pragma unroll
            for (int i = 0; i < 64; i++) {
                int chunk = lane + 32*i;
                int row = chunk >> 3, seg = chunk & 7;
                const __nv_bfloat16* src = (row < MT) ? (Ak + (size_t)row*Kd + seg*8)
                                                      : (Bk + (size_t)(row-MT)*Kd + seg*8);
                cpasync16(stb + (uint32_t)(row*TSTB + seg*16), src);
            }
            cpasync_arrive_noinc(barb + 16*s);
            if (++s == NSTG) { s = 0; ph ^= 1; }
        }
        return;
    }

    // ---- consumers: 8 warps, warp tile 32(M) x 64(N), k16 steps ----
    int wm = wid & 3, wn = wid >> 2;
    int g = lane >> 2, tig = lane & 3;
    int lj = lane & 7, lsub = lane >> 3;
    // A frag (m16k16): mats (r0-7,k0-7),(r8-15,k0-7),(r0-7,k8-15),(r8-15,k8-15)
    uint32_t a_lane_off = (uint32_t)(((lsub & 1)*8 + lj)*TSTB + (lsub >> 1)*16);
    // B frag pair: mats (n0-7,k0-7),(n0-7,k8-15),(n8-15,k0-7),(n8-15,k8-15)
    uint32_t b_lane_off = (uint32_t)((((lsub >> 1)&1)*8 + lj)*TSTB + (lsub & 1)*16);

    float acc[2][8][4];
#pragma unroll
    for (int mi = 0; mi < 2; mi++)
#pragma unroll
        for (int ni = 0; ni < 8; ni++)
#pragma unroll
            for (int c = 0; c < 4; c++) acc[mi][ni][c] = 0.f;

    int s = 0, ph = 0;
    for (int kt = 0; kt < nk; kt++) {
        mbar_wait(barb + 16*s, ph);
        uint32_t a_tile = sbase + (uint32_t)(s*STG_BYTES) + (uint32_t)(wm*32*TSTB) + a_lane_off;
        uint32_t b_tile = sbase + (uint32_t)(s*STG_BYTES) + (uint32_t)((MT + wn*64)*TSTB) + b_lane_off;
#pragma unroll
        for (int ks = 0; ks < 4; ks++) {
            uint32_t kb = ks*32;             // 16 bf16 = 32 bytes per step
            uint32_t af[2][4];
#pragma unroll
            for (int mi = 0; mi < 2; mi++)
                ldsm4(af[mi][0], af[mi][1], af[mi][2], af[mi][3],
                      a_tile + (uint32_t)(mi*16*TSTB) + kb);
            // staggered B: one ldsm4 (2 ni) at a time to cap live registers
#pragma unroll
            for (int p = 0; p < 4; p++) {
                uint32_t bfp[2][2];
                ldsm4(bfp[0][0], bfp[0][1], bfp[1][0], bfp[1][1],
                      b_tile + (uint32_t)(p*16*TSTB) + kb);
#pragma unroll
                for (int mi = 0; mi < 2; mi++)
#pragma unroll
                    for (int nii = 0; nii < 2; nii++)
                        mma16(acc[mi][2*p + nii], af[mi], bfp[nii]);
            }
        }
        if (lane == 0) mbar_arrive(barb + 16*s + 8);
        if (++s == NSTG) { s = 0; ph ^= 1; }
    }

    // ---- epilogue ----
#pragma unroll
    for (int mi = 0; mi < 2; mi++) {
        int r0 = bm*MT + wm*32 + mi*16 + g;
#pragma unroll
        for (int ni = 0; ni < 8; ni++) {
            int col = bn*NTB + wn*64 + ni*8 + tig*2;
            float2 bv = *(const float2*)(bias + col);
#pragma unroll
            for (int hrow = 0; hrow < 2; hrow++) {
                int r = r0 + hrow*8;
                float o0 = acc[mi][ni][hrow*2+0] + bv.x;
                float o1 = acc[mi][ni][hrow*2+1] + bv.y;
                if (EPI == 1) {
                    __nv_bfloat162 pv = __floats2bfloat162_rn(gelu_f(o0), gelu_f(o1));
                    *(__nv_bfloat162*)((__nv_bfloat16*)C + (size_t)r * Ntot + col) = pv;
                } else {
                    if (EPI == 2) {
                        float2 rv = *(const float2*)(res + (size_t)r * Ntot + col);
                        o0 += rv.x; o1 += rv.y;
                    }
                    float2 ov; ov.x = o0; ov.y = o1;
                    *(float2*)(C + (size_t)r * Ntot + col) = ov;
                }
            }
        }
    }
}

// ---------------- fused: weight transpose([K][N]->[N][K]) + bf16 round + router ----------------
#define TRT_TILES 24576
__global__ void trans_router_kernel(
    const float* __restrict__ x, const float* __restrict__ wr, const float* __restrict__ br,
    const float* __restrict__ wq, const float* __restrict__ wo,
    const float* __restrict__ w1s, const float* __restrict__ w2s)
{
    int blk = blockIdx.x;
    if (blk < TRT_TILES) {
        __shared__ float t[32][33];
        const float* src; __nv_bfloat16* dst; int Kd, N, tile;
        if (blk < 6144) {
            int l = blk / 3072; tile = blk % 3072;
            src = wq + (size_t)l*DD*3*DD; dst = g_wt + WT_QKV + (size_t)l*3*DD*DD;
            Kd = DD; N = 3*DD;
        } else if (blk < 8192) {
            int r = blk - 6144; int l = r / 1024; tile = r % 1024;
            src = wo + (size_t)l*DD*DD; dst = g_wt + WT_O + (size_t)l*DD*DD;
            Kd = DD; N = DD;
        } else if (blk < 16384) {
            int r = blk - 8192; int l = r / 4096; tile = r % 4096;
            src = w1s + (size_t)l*DD*FF; dst = g_wt + WT_W1 + (size_t)l*DD*FF;
            Kd = DD; N = FF;
        } else {
            int r = blk - 16384; int l = r / 4096; tile = r % 4096;
            src = w2s + (size_t)l*FF*DD; dst = g_wt + WT_W2 + (size_t)l*FF*DD;
            Kd = FF; N = DD;
        }
        int ntn = N >> 5;
        int k0 = (tile / ntn) << 5, n0 = (tile % ntn) << 5;
        int tx = threadIdx.x & 31, ty = threadIdx.x >> 5;
#pragma unroll
        for (int i = 0; i < 4; i++)
            t[ty + 8*i][tx] = src[(size_t)(k0 + ty + 8*i) * N + n0 + tx];
        __syncthreads();
#pragma unroll
        for (int i = 0; i < 4; i++)
            dst[(size_t)(n0 + ty + 8*i) * Kd + k0 + tx] = __float2bfloat16_rn(t[tx][ty + 8*i]);
    } else {
        int row  = (blk - TRT_TILES) * 8 + (threadIdx.x >> 5);
        int lane = threadIdx.x & 31;
        const float4* xr = (const float4*)(x + (size_t)row * DD);
        const float4* wv = (const float4*)wr;
        float s = 0.f;
#pragma unroll
        for (int i = 0; i < 8; i++) {
            int c = lane + i * 32;
            float4 a = xr[c], b = wv[c];
            s += a.x*b.x + a.y*b.y + a.z*b.z + a.w*b.w;
        }
#pragma unroll
        for (int o = 16; o; o >>= 1) s += __shfl_xor_sync(0xffffffffu, s, o);
        if (!lane) g_logits[row] = s + br[0];
    }
}

// ---------------- exact top-K via radix select + scan (also builds inverse map) ----------------
__global__ void topk_kernel() {
    __shared__ unsigned key[TT];
    __shared__ int s_cnt;
    __shared__ int s_scan[1024];
    int b = blockIdx.x, tid = threadIdx.x;

    for (int t = tid; t < TT; t += 1024) {
        unsigned u = __float_as_uint(g_logits[b*TT + t]);
        u = (u & 0x80000000u) ? ~u : (u | 0x80000000u);
        key[t] = u;
    }
    __syncthreads();

    unsigned prefix = 0; int needed = KK;
    for (int bit = 31; bit >= 0; --bit) {
        if (!tid) s_cnt = 0;
        __syncthreads();
        unsigned cand = prefix | (1u << bit);
        unsigned mask = ~((1u << bit) - 1u);
        int loc = 0;
        for (int t = tid; t < TT; t += 1024) loc += ((key[t] & mask) == cand);
#pragma unroll
        for (int o = 16; o; o >>= 1) loc += __shfl_xor_sync(0xffffffffu, loc, o);
        if ((tid & 31) == 0) atomicAdd(&s_cnt, loc);
        __syncthreads();
        int c = s_cnt;
        if (needed <= c) prefix = cand; else needed -= c;
        __syncthreads();
    }
    int base = tid * 4;
    int vals[4]; int run = 0;
#pragma unroll
    for (int i = 0; i < 4; i++) {
        unsigned k2 = key[base + i];
        int gt = (k2 > prefix), eq = (k2 == prefix);
        vals[i] = run;
        run += (gt << 16) | eq;
    }
    s_scan[tid] = run;
    __syncthreads();
    for (int off = 1; off < 1024; off <<= 1) {
        int v = (tid >= off) ? s_scan[tid - off] : 0;
        __syncthreads();
        s_scan[tid] += v;
        __syncthreads();
    }
    int excl = tid ? s_scan[tid - 1] : 0;
#pragma unroll
    for (int i = 0; i < 4; i++) {
        int t = base + i;
        unsigned k2 = key[t];
        int pre = excl + vals[i];
        int gtB = pre >> 16, eqB = pre & 0xFFFF;
        bool sel = (k2 > prefix) || (k2 == prefix && eqB < needed);
        int pos = gtB + min(eqB, needed);
        g_pos[b*TT + t] = sel ? pos : -1;
        if (sel) {
            g_idx[b*KK + pos] = t;
            float lg = g_logits[b*TT + t];
            g_gate[b*KK + pos] = 1.f / (1.f + expf(-lg));
        }
    }
}

// ---------------- fused gather + layer-0 ln1 (bf16 out) ----------------
__global__ void gather_ln_kernel(const float* __restrict__ x,
                                 const float* __restrict__ scale,
                                 const float* __restrict__ bias) {
    int row = blockIdx.x, tid = threadIdx.x;
    int b = row / KK;
    int t = g_idx[row];
    float4 v = ((const float4*)(x + ((size_t)b*TT + t) * DD))[tid];
    ((float4*)(g_h + (size_t)row * DD))[tid] = v;

    float s  = v.x + v.y + v.z + v.w;
    float sq = v.x*v.x + v.y*v.y + v.z*v.z + v.w*v.w;
#pragma unroll
    for (int o = 16; o; o >>= 1) {
        s  += __shfl_xor_sync(0xffffffffu, s, o);
        sq += __shfl_xor_sync(0xffffffffu, sq, o);
    }
    __shared__ float ss[8], sq2[8];
    if ((tid & 31) == 0) { ss[tid >> 5] = s; sq2[tid >> 5] = sq; }
    __syncthreads();
    float S = 0.f, SQ = 0.f;
#pragma unroll
    for (int i = 0; i < 8; i++) { S += ss[i]; SQ += sq2[i]; }
    float mean = S * (1.f / DD);
    float var  = SQ * (1.f / DD) - mean * mean;
    float inv  = rsqrtf(var + 1e-5f);
    float4 sc = ((const float4*)scale)[tid];
    float4 bi = ((const float4*)bias)[tid];
    __nv_bfloat162 p0 = __floats2bfloat162_rn((v.x - mean) * inv * sc.x + bi.x,
                                              (v.y - mean) * inv * sc.y + bi.y);
    __nv_bfloat162 p1 = __floats2bfloat162_rn((v.z - mean) * inv * sc.z + bi.z,
                                              (v.w - mean) * inv * sc.w + bi.w);
    uint2 pk;
    pk.x = *reinterpret_cast<uint32_t*>(&p0);
    pk.y = *reinterpret_cast<uint32_t*>(&p1);
    ((uint2*)(g_a + (size_t)row * DD))[tid] = pk;
}

// ---------------- layernorm (fp32 in -> bf16 out) ----------------
__global__ void ln_kernel(const float* __restrict__ in, const float* __restrict__ scale,
                          const float* __restrict__ bias, __nv_bfloat16* __restrict__ out) {
    int row = blockIdx.x, tid = threadIdx.x;
    float4 v = ((const float4*)(in + (size_t)row * DD))[tid];
    float s  = v.x + v.y + v.z + v.w;
    float sq = v.x*v.x + v.y*v.y + v.z*v.z + v.w*v.w;
#pragma unroll
    for (int o = 16; o; o >>= 1) {
        s  += __shfl_xor_sync(0xffffffffu, s, o);
        sq += __shfl_xor_sync(0xffffffffu, sq, o);
    }
    __shared__ float ss[8], sq2[8];
    if ((tid & 31) == 0) { ss[tid >> 5] = s; sq2[tid >> 5] = sq; }
    __syncthreads();
    float S = 0.f, SQ = 0.f;
#pragma unroll
    for (int i = 0; i < 8; i++) { S += ss[i]; SQ += sq2[i]; }
    float mean = S * (1.f / DD);
    float var  = SQ * (1.f / DD) - mean * mean;
    float inv  = rsqrtf(var + 1e-5f);
    float4 sc = ((const float4*)scale)[tid];
    float4 bi = ((const float4*)bias)[tid];
    __nv_bfloat162 p0 = __floats2bfloat162_rn((v.x - mean) * inv * sc.x + bi.x,
                                              (v.y - mean) * inv * sc.y + bi.y);
    __nv_bfloat162 p1 = __floats2bfloat162_rn((v.z - mean) * inv * sc.z + bi.z,
                                              (v.w - mean) * inv * sc.w + bi.w);
    uint2 pk;
    pk.x = *reinterpret_cast<uint32_t*>(&p0);
    pk.y = *reinterpret_cast<uint32_t*>(&p1);
    ((uint2*)(out + (size_t)row * DD))[tid] = pk;
}

// ---------------- single-pass output: copy + gated scatter-add + tail ----------------
#define OUT_MAIN_BLOCKS 8192   // BB*TT*DD/4/256
__global__ void out_kernel(const float* __restrict__ x, float* __restrict__ out) {
    int blk = blockIdx.x;
    if (blk < OUT_MAIN_BLOCKS) {
        size_t i = (size_t)blk * 256 + threadIdx.x;   // float4 index
        int row = (int)(i >> 8);
        int b = row >> 12;
        int t = row & (TT - 1);
        float4 v = ((const float4*)x)[i];
        int pos = g_pos[b*TT + t];
        if (pos >= 0) {
            float gg = g_gate[b*KK + pos];
            float4 hv = ((const float4*)(g_h + ((size_t)b*KK + pos) * DD))[i & 255];
            v.x += gg*hv.x; v.y += gg*hv.y; v.z += gg*hv.z; v.w += gg*hv.w;
        }
        ((float4*)out)[i] = v;
    } else {
        int i = (blk - OUT_MAIN_BLOCKS) * 256 + threadIdx.x;
        size_t base = (size_t)BB * TT * DD;
        if (i < BB*KK) out[base + i] = (float)g_idx[i];
        if (i < BB*TT) out[base + BB*KK + i] = g_logits[i];
    }
}

// ---------------- flash attention: mma.sync tf32, causal, 64x64 tiles ----------------
#define AQ 4352        // 64*68
#define AK 4352
#define AP 4352
#define AV 4608        // 64*72
#define ATTN2_SMEM ((AQ + 2*AK + AP + 2*AV)*4)

__global__ __launch_bounds__(128) void attn_mma_kernel() {
    extern __shared__ __align__(16) float sm[];
    float* Qs = sm;
    float* Ks = sm + AQ;                 // 2 stages
    float* Ps = sm + AQ + 2*AK;
    float* Vs = sm + AQ + 2*AK + AP;     // 2 stages
    uint32_t q_addr = smem_u32(Qs);
    uint32_t k_addr = smem_u32(Ks);
    uint32_t v_addr = smem_u32(Vs);

    int tid = threadIdx.x;
    int wid = tid >> 5, lane = tid & 31;
    int g = lane >> 2, tig = lane & 3;
    int qb = gridDim.x - 1 - blockIdx.x;      // heavy tiles first
    int bh = blockIdx.y;
    int b = bh >> 4, h = bh & 15;
    const float* qkv = g_qkv + (size_t)b * KK * 3 * DD + h * DHD;  // row stride 3*DD

    auto load_kv = [&](int s, int jt) {
#pragma unroll
        for (int i = 0; i < 8; i++) {
            int chunk = tid + 128*i;
            int r = chunk >> 4, c4 = chunk & 15;
            const float* src = qkv + (size_t)(jt*64 + r) * (3*DD) + c4*4;
            cpasync16(k_addr + (uint32_t)(s*AK + r*68)*4 + c4*16, src + DD);
            cpasync16(v_addr + (uint32_t)(s*AV + r*72)*4 + c4*16, src + 2*DD);
        }
        cp_commit();
    };

#pragma unroll
    for (int i = 0; i < 8; i++) {
        int chunk = tid + 128*i;
        int r = chunk >> 4, c4 = chunk & 15;
        cpasync16(q_addr + (uint32_t)(r*68)*4 + c4*16,
                  qkv + (size_t)(qb*64 + r) * (3*DD) + c4*4);
    }
    load_kv(0, 0);

    float mrow[2] = {-3.0e38f, -3.0e38f};
    float lrow[2] = {0.f, 0.f};
    float accO[8][4];
#pragma unroll
    for (int ni = 0; ni < 8; ni++)
#pragma unroll
        for (int c = 0; c < 4; c++) accO[ni][c] = 0.f;

    int qrow = wid*16 + g;

    for (int jt = 0; jt <= qb; jt++) {
        if (jt < qb) load_kv((jt+1) & 1, jt+1);
        if (jt < qb) asm volatile("cp.async.wait_group 1;" ::: "memory");
        else         asm volatile("cp.async.wait_group 0;" ::: "memory");
        __syncthreads();

        const float* ks = Ks + (jt & 1)*AK;
        const float* vs = Vs + (jt & 1)*AV;

        float accS[8][4];
#pragma unroll
        for (int ni = 0; ni < 8; ni++)
#pragma unroll
            for (int c = 0; c < 4; c++) accS[ni][c] = 0.f;
#pragma unroll
        for (int k8 = 0; k8 < 8; k8++) {
            int k = k8*8;
            float af[4];
            af[0] = Qs[(qrow)*68 + k + tig];
            af[1] = Qs[(qrow+8)*68 + k + tig];
            af[2] = Qs[(qrow)*68 + k + tig + 4];
            af[3] = Qs[(qrow+8)*68 + k + tig + 4];
#pragma unroll
            for (int ni = 0; ni < 8; ni++) {
                float bf[2];
                bf[0] = ks[(8*ni + g)*68 + k + tig];
                bf[1] = ks[(8*ni + g)*68 + k + tig + 4];
                mma8(accS[ni], af, bf);
            }
        }

        bool diag = (jt == qb);
#pragma unroll
        for (int ni = 0; ni < 8; ni++)
#pragma unroll
            for (int c = 0; c < 4; c++) {
                float s = accS[ni][c] * 0.125f;
                if (diag) {
                    int kg = 8*ni + 2*tig + (c & 1);
                    int qg = wid*16 + g + 8*(c >> 1);
                    if (kg > qg) s = -3.0e38f;
                }
                accS[ni][c] = s;
            }

#pragma unroll
        for (int r = 0; r < 2; r++) {
            float rm = -3.0e38f;
#pragma unroll
            for (int ni = 0; ni < 8; ni++)
                rm = fmaxf(rm, fmaxf(accS[ni][2*r], accS[ni][2*r+1]));
            rm = fmaxf(rm, __shfl_xor_sync(0xffffffffu, rm, 1));
            rm = fmaxf(rm, __shfl_xor_sync(0xffffffffu, rm, 2));
            float mn = fmaxf(mrow[r], rm);
            float corr = __expf(mrow[r] - mn);
            mrow[r] = mn;
            float rs = 0.f;
#pragma unroll
            for (int ni = 0; ni < 8; ni++) {
                float p0 = __expf(accS[ni][2*r]   - mn);
                float p1 = __expf(accS[ni][2*r+1] - mn);
                rs += p0 + p1;
                accS[ni][2*r]   = tf32rn(p0);
                accS[ni][2*r+1] = tf32rn(p1);
            }
            rs += __shfl_xor_sync(0xffffffffu, rs, 1);
            rs += __shfl_xor_sync(0xffffffffu, rs, 2);
            lrow[r] = lrow[r] * corr + rs;
#pragma unroll
            for (int ni = 0; ni < 8; ni++) {
                accO[ni][2*r]   *= corr;
                accO[ni][2*r+1] *= corr;
            }
        }

#pragma unroll
        for (int ni = 0; ni < 8; ni++) {
            float2 p0; p0.x = accS[ni][0]; p0.y = accS[ni][1];
            float2 p1; p1.x = accS[ni][2]; p1.y = accS[ni][3];
            *(float2*)&Ps[(qrow)*68 + 8*ni + 2*tig]   = p0;
            *(float2*)&Ps[(qrow+8)*68 + 8*ni + 2*tig] = p1;
        }
        __syncwarp();

#pragma unroll
        for (int k8 = 0; k8 < 8; k8++) {
            int k = k8*8;
            float af[4];
            af[0] = Ps[(qrow)*68 + k + tig];
            af[1] = Ps[(qrow+8)*68 + k + tig];
            af[2] = Ps[(qrow)*68 + k + tig + 4];
            af[3] = Ps[(qrow+8)*68 + k + tig + 4];
#pragma unroll
            for (int ni = 0; ni < 8; ni++) {
                float bf[2];
                bf[0] = vs[(k + tig)*72 + 8*ni + g];
                bf[1] = vs[(k + tig + 4)*72 + 8*ni + g];
                mma8(accO[ni], af, bf);
            }
        }
        __syncthreads();
    }

    // normalize + write bf16 (feeds o-proj GEMM)
    __nv_bfloat16* op = g_attn + (size_t)b * KK * DD + h * DHD;
#pragma unroll
    for (int r = 0; r < 2; r++) {
        float inv = 1.f / lrow[r];
        int row = qb*64 + wid*16 + g + 8*r;
#pragma unroll
        for (int ni = 0; ni < 8; ni++) {
            __nv_bfloat162 ov = __floats2bfloat162_rn(accO[ni][2*r]   * inv,
                                                      accO[ni][2*r+1] * inv);
            *(__nv_bfloat162*)(op + (size_t)row * DD + 8*ni + 2*tig) = ov;
        }
    }
}

// ---------------- launch ----------------
extern "C" void kernel_launch(void* const* d_in, const int* in_sizes, int n_in,
                              void* d_out, int out_size) {
    const float* x        = (const float*)d_in[0];
    const float* w_router = (const float*)d_in[1];
    const float* b_router = (const float*)d_in[2];
    const float* ln1_s    = (const float*)d_in[3];
    const float* ln1_b    = (const float*)d_in[4];
    const float* w_qkv    = (const float*)d_in[5];
    const float* b_qkv    = (const float*)d_in[6];
    const float* w_o      = (const float*)d_in[7];
    const float* b_o      = (const float*)d_in[8];
    const float* ln2_s    = (const float*)d_in[9];
    const float* ln2_b    = (const float*)d_in[10];
    const float* w1       = (const float*)d_in[11];
    const float* b1       = (const float*)d_in[12];
    const float* w2       = (const float*)d_in[13];
    const float* b2       = (const float*)d_in[14];
    float* out = (float*)d_out;

    float *p_h, *p_qkv;
    __nv_bfloat16 *p_a, *p_attn, *p_ffn, *p_wt;
    cudaGetSymbolAddress((void**)&p_h,    g_h);
    cudaGetSymbolAddress((void**)&p_a,    g_a);
    cudaGetSymbolAddress((void**)&p_qkv,  g_qkv);
    cudaGetSymbolAddress((void**)&p_attn, g_attn);
    cudaGetSymbolAddress((void**)&p_ffn,  g_ffn);
    cudaGetSymbolAddress((void**)&p_wt,   g_wt);

    cudaFuncSetAttribute(attn_mma_kernel, cudaFuncAttributeMaxDynamicSharedMemorySize,
                         ATTN2_SMEM);
    cudaFuncSetAttribute(mma_gemm<1>, cudaFuncAttributeMaxDynamicSharedMemorySize, GEMM_SMEM);
    cudaFuncSetAttribute(mma_gemm<2>, cudaFuncAttributeMaxDynamicSharedMemorySize, GEMM_SMEM);
    cudaFuncSetAttribute(mma_gemm<3>, cudaFuncAttributeMaxDynamicSharedMemorySize, GEMM_SMEM);

    // 1: weight transpose + bf16 round + router (fused)
    trans_router_kernel<<<TRT_TILES + BB*TT/8, 256>>>(
        x, w_router, b_router, w_qkv, w_o, w1, w2);
    // 2: exact top-K
    topk_kernel<<<BB, 1024>>>();
    // 3: gather + layer-0 ln1
    gather_ln_kernel<<<MROWS, 256>>>(x, ln1_s, ln1_b);

    for (int l = 0; l < LL; l++) {
        if (l > 0)
            ln_kernel<<<MROWS, 256>>>(p_h, ln1_s + l*DD, ln1_b + l*DD, p_a);
        // 4 (for l=0): qkv GEMM -> profiled launch
        mma_gemm<3><<<dim3(3*DD/NTB, MROWS/MT), GEMM_THREADS, GEMM_SMEM>>>(
            p_a, p_wt + WT_QKV + (size_t)l*3*DD*DD, b_qkv + (size_t)l*3*DD, nullptr,
            p_qkv, DD, 3*DD);
        attn_mma_kernel<<<dim3(KK/64, BB*HH), 128, ATTN2_SMEM>>>();
        mma_gemm<2><<<dim3(DD/NTB, MROWS/MT), GEMM_THREADS, GEMM_SMEM>>>(
            p_attn, p_wt + WT_O + (size_t)l*DD*DD, b_o + (size_t)l*DD, p_h,
            p_h, DD, DD);
        ln_kernel<<<MROWS, 256>>>(p_h, ln2_s + l*DD, ln2_b + l*DD, p_a);
        mma_gemm<1><<<dim3(FF/NTB, MROWS/MT), GEMM_THREADS, GEMM_SMEM>>>(
            p_a, p_wt + WT_W1 + (size_t)l*FF*DD, b1 + (size_t)l*FF, nullptr,
            (float*)p_ffn, DD, FF);
        mma_gemm<2><<<dim3(DD/NTB, MROWS/MT), GEMM_THREADS, GEMM_SMEM>>>(
            p_ffn, p_wt + WT_W2 + (size_t)l*DD*FF, b2 + (size_t)l*DD, p_h,
            p_h, FF, DD);
    }

    long long full = (long long)BB*TT*DD + (long long)BB*KK + (long long)BB*TT;
    int tail_blocks = ((long long)out_size >= full) ? 32 : 0;
    out_kernel<<<OUT_MAIN_BLOCKS + tail_blocks, 256>>>(x, out);
}

// round 16
// speedup vs baseline: 1.3458x; 1.3458x over previous
#include <cuda_runtime.h>
#include <cuda_bf16.h>
#include <math.h>
#include <stdint.h>

#define BB 2
#define TT 4096
#define DD 1024
#define LL 2
#define HH 16
#define FF 4096
#define KK 2048
#define DHD 64
#define MROWS (BB*KK)   // 4096 (batch folded into M)

// ---------------- scratch (static device globals; no allocations) ----------------
__device__ float g_logits[BB*TT];
__device__ int   g_idx[BB*KK];
__device__ int   g_pos[BB*TT];     // token -> k-position (or -1)
__device__ float g_gate[BB*KK];
__device__ float g_h[BB*KK*DD];
__device__ __nv_bfloat16 g_a[BB*KK*DD];
__device__ float g_qkv[BB*KK*3*DD];
__device__ __nv_bfloat16 g_attn[BB*KK*DD];
__device__ __nv_bfloat16 g_ffn[(size_t)BB*KK*FF];

// transposed ([N][K] k-contiguous) bf16 weights
#define WT_QKV 0
#define WT_O   (LL*DD*3*DD)
#define WT_W1  (WT_O + LL*DD*DD)
#define WT_W2  (WT_W1 + LL*DD*FF)
#define WT_TOT (WT_W2 + LL*FF*DD)
__device__ __nv_bfloat16 g_wt[WT_TOT];

// ---------------- helpers ----------------
__device__ __forceinline__ uint32_t smem_u32(const void* p) {
    uint32_t a;
    asm("{ .reg .u64 t; cvta.to.shared.u64 t, %1; cvt.u32.u64 %0, t; }" : "=r"(a) : "l"(p));
    return a;
}
__device__ __forceinline__ float tf32rn(float x) {
    uint32_t u;
    asm("cvt.rna.tf32.f32 %0, %1;" : "=r"(u) : "f"(x));
    return __uint_as_float(u);
}
__device__ __forceinline__ void cpasync16(uint32_t dst, const void* src) {
    asm volatile("cp.async.cg.shared.global [%0], [%1], 16;" :: "r"(dst), "l"(src) : "memory");
}
__device__ __forceinline__ void cp_commit() {
    asm volatile("cp.async.commit_group;" ::: "memory");
}
__device__ __forceinline__ void mbar_init(uint32_t a, uint32_t cnt) {
    asm volatile("mbarrier.init.shared.b64 [%0], %1;" :: "r"(a), "r"(cnt) : "memory");
}
__device__ __forceinline__ void mbar_arrive(uint32_t a) {
    asm volatile("mbarrier.arrive.shared.b64 _, [%0];" :: "r"(a) : "memory");
}
__device__ __forceinline__ void mbar_wait(uint32_t a, uint32_t parity) {
    asm volatile(
        "{\n\t.reg .pred P;\n\tWL%=:\n\t"
        "mbarrier.try_wait.parity.acquire.cta.shared::cta.b64 P, [%0], %1;\n\t"
        "@P bra WD%=;\n\tbra WL%=;\n\tWD%=:\n\t}"
        :: "r"(a), "r"(parity) : "memory");
}
__device__ __forceinline__ void cpasync_arrive_noinc(uint32_t mbar) {
    asm volatile("cp.async.mbarrier.arrive.noinc.shared.b64 [%0];" :: "r"(mbar) : "memory");
}
__device__ __forceinline__ void ldsm4(uint32_t& r0, uint32_t& r1, uint32_t& r2, uint32_t& r3,
                                      uint32_t addr) {
    asm volatile("ldmatrix.sync.aligned.m8n8.x4.shared.b16 {%0,%1,%2,%3}, [%4];"
        : "=r"(r0), "=r"(r1), "=r"(r2), "=r"(r3) : "r"(addr));
}
__device__ __forceinline__ void mma16(float* d, const uint32_t* a, const uint32_t* b) {
    asm volatile("mma.sync.aligned.m16n8k16.row.col.f32.bf16.bf16.f32 "
        "{%0,%1,%2,%3}, {%4,%5,%6,%7}, {%8,%9}, {%0,%1,%2,%3};"
        : "+f"(d[0]), "+f"(d[1]), "+f"(d[2]), "+f"(d[3])
        : "r"(a[0]), "r"(a[1]), "r"(a[2]), "r"(a[3]), "r"(b[0]), "r"(b[1]));
}
__device__ __forceinline__ void mma8(float* d, const float* a, const float* b) {
    asm volatile("mma.sync.aligned.m16n8k8.row.col.f32.tf32.tf32.f32 "
        "{%0,%1,%2,%3}, {%4,%5,%6,%7}, {%8,%9}, {%0,%1,%2,%3};"
        : "+f"(d[0]), "+f"(d[1]), "+f"(d[2]), "+f"(d[3])
        : "r"(__float_as_uint(a[0])), "r"(__float_as_uint(a[1])),
          "r"(__float_as_uint(a[2])), "r"(__float_as_uint(a[3])),
          "r"(__float_as_uint(b[0])), "r"(__float_as_uint(b[1])));
}

__device__ __forceinline__ float gelu_f(float x) {
    float x3 = x * x * x;
    float t = tanhf(0.7978845608028654f * (x + 0.044715f * x3));
    return 0.5f * x * (1.f + t);
}

// ---------------- warp-specialized bf16 m16n8k16 GEMM ----------------
// C = A(M x Kd) @ Wt^T + bias.  A: [M][Kd] bf16; Wt: [Ntot][Kd] bf16.
// CTA tile 128x64. 8 consumer warps (32x32 tiles) + 2 producer warps.
// 4-stage cp.async ring (K-chunk 64), mbarrier full/done; no CTA barrier in mainloop.
#define MT 128
#define NTB 64
#define KCHB 64                          // bf16 k elements per stage
#define TSTB 144                         // row stride in BYTES (72 bf16)
#define STG_BYTES ((MT+NTB)*TSTB)        // 27648
#define NSTG 4
#define GEMM_SMEM (NSTG*STG_BYTES)       // 110592 -> 2 CTAs/SM
#define GEMM_THREADS 320                 // 256 consumer + 64 producer

// EPI: 0 = bias, 1 = bias+gelu -> bf16 out, 2 = bias+residual (fp32), 3 = bias+tf32 round (fp32)
template <int EPI>
__global__ __launch_bounds__(GEMM_THREADS, 2) void mma_gemm(
    const __nv_bfloat16* __restrict__ A, const __nv_bfloat16* __restrict__ Wt,
    const float* __restrict__ bias, const float* __restrict__ res,
    float* __restrict__ C, int Kd, int Ntot)
{
    extern __shared__ __align__(16) char smc[];
    __shared__ __align__(8) uint64_t mbars[2*NSTG];   // full[s], done[s]
    uint32_t sbase = smem_u32(smc);
    uint32_t barb  = smem_u32(mbars);

    int tid = threadIdx.x;
    int bn = blockIdx.x, bm = blockIdx.y;
    int wid = tid >> 5, lane = tid & 31;
    int nk = Kd / KCHB;

    if (tid == 0) {
        for (int s = 0; s < NSTG; s++) {
            mbar_init(barb + 16*s, 64);      // full: 64 producer arrivals (noinc)
            mbar_init(barb + 16*s + 8, 8);   // done: 8 consumer-warp arrivals
        }
    }
    __syncthreads();

    if (wid >= 8) {
        // ---- producers: 64 threads fill stages (192 rows x 128 B) ----
        int t = tid - 256;
        const __nv_bfloat16* Ag = A + (size_t)(bm*MT) * Kd;
        const __nv_bfloat16* Bg = Wt + (size_t)(bn*NTB) * Kd;
        int s = 0, ph = 1;
        for (int kt = 0; kt < nk; kt++) {
            mbar_wait(barb + 16*s + 8, ph);
            uint32_t stb = sbase + (uint32_t)(s*STG_BYTES);
            const __nv_bfloat16* Ak = Ag + kt*KCHB;
            const __nv_bfloat16* Bk = Bg + kt*KCHB;
#pragma unroll
            for (int i = 0; i < 24; i++) {
                int chunk = t + 64*i;
                int row = chunk >> 3, seg = chunk & 7;
                const __nv_bfloat16* src = (row < MT) ? (Ak + (size_t)row*Kd + seg*8)
                                                      : (Bk + (size_t)(row-MT)*Kd + seg*8);
                cpasync16(stb + (uint32_t)(row*TSTB + seg*16), src);
            }
            cpasync_arrive_noinc(barb + 16*s);
            if (++s == NSTG) { s = 0; ph ^= 1; }
        }
        return;
    }

    // ---- consumers: 8 warps, warp tile 32(M) x 32(N), k16 steps ----
    int wm = wid & 3, wn = wid >> 2;
    int g = lane >> 2, tig = lane & 3;
    int lj = lane & 7, lsub = lane >> 3;
    // A frag (m16k16): mats (r0-7,k0-7),(r8-15,k0-7),(r0-7,k8-15),(r8-15,k8-15)
    uint32_t a_lane_off = (uint32_t)(((lsub & 1)*8 + lj)*TSTB + (lsub >> 1)*16);
    // B frags x2 ni: mats (n0-7,k0-7),(n0-7,k8-15),(n8-15,k0-7),(n8-15,k8-15)
    uint32_t b_lane_off = (uint32_t)((((lsub >> 1)&1)*8 + lj)*TSTB + (lsub & 1)*16);

    float acc[2][4][4];
#pragma unroll
    for (int mi = 0; mi < 2; mi++)
#pragma unroll
        for (int ni = 0; ni < 4; ni++)
#pragma unroll
            for (int c = 0; c < 4; c++) acc[mi][ni][c] = 0.f;

    int s = 0, ph = 0;
    for (int kt = 0; kt < nk; kt++) {
        mbar_wait(barb + 16*s, ph);
        uint32_t a_tile = sbase + (uint32_t)(s*STG_BYTES) + (uint32_t)(wm*32*TSTB) + a_lane_off;
        uint32_t b_tile = sbase + (uint32_t)(s*STG_BYTES) + (uint32_t)((MT + wn*32)*TSTB) + b_lane_off;
#pragma unroll
        for (int ks = 0; ks < 4; ks++) {
            uint32_t kb = ks*32;             // 16 bf16 = 32 bytes per step
            uint32_t af[2][4];
#pragma unroll
            for (int mi = 0; mi < 2; mi++)
                ldsm4(af[mi][0], af[mi][1], af[mi][2], af[mi][3],
                      a_tile + (uint32_t)(mi*16*TSTB) + kb);
            uint32_t bf[4][2];
#pragma unroll
            for (int p = 0; p < 2; p++)
                ldsm4(bf[2*p][0], bf[2*p][1], bf[2*p+1][0], bf[2*p+1][1],
                      b_tile + (uint32_t)(p*16*TSTB) + kb);
#pragma unroll
            for (int mi = 0; mi < 2; mi++)
#pragma unroll
                for (int ni = 0; ni < 4; ni++)
                    mma16(acc[mi][ni], af[mi], bf[ni]);
        }
        if (lane == 0) mbar_arrive(barb + 16*s + 8);
        if (++s == NSTG) { s = 0; ph ^= 1; }
    }

    // ---- epilogue ----
#pragma unroll
    for (int mi = 0; mi < 2; mi++) {
        int r0 = bm*MT + wm*32 + mi*16 + g;
#pragma unroll
        for (int ni = 0; ni < 4; ni++) {
            int col = bn*NTB + wn*32 + ni*8 + tig*2;
            float2 bv = *(const float2*)(bias + col);
#pragma unroll
            for (int hrow = 0; hrow < 2; hrow++) {
                int r = r0 + hrow*8;
                float o0 = acc[mi][ni][hrow*2+0] + bv.x;
                float o1 = acc[mi][ni][hrow*2+1] + bv.y;
                if (EPI == 1) {
                    __nv_bfloat162 pv = __floats2bfloat162_rn(gelu_f(o0), gelu_f(o1));
                    *(__nv_bfloat162*)((__nv_bfloat16*)C + (size_t)r * Ntot + col) = pv;
                } else {
                    if (EPI == 2) {
                        float2 rv = *(const float2*)(res + (size_t)r * Ntot + col);
                        o0 += rv.x; o1 += rv.y;
                    }
                    if (EPI == 3) { o0 = tf32rn(o0); o1 = tf32rn(o1); }
                    float2 ov; ov.x = o0; ov.y = o1;
                    *(float2*)(C + (size_t)r * Ntot + col) = ov;
                }
            }
        }
    }
}

// ---------------- fused: weight transpose([K][N]->[N][K]) + bf16 round + router ----------------
#define TRT_TILES 24576
__global__ void trans_router_kernel(
    const float* __restrict__ x, const float* __restrict__ wr, const float* __restrict__ br,
    const float* __restrict__ wq, const float* __restrict__ wo,
    const float* __restrict__ w1s, const float* __restrict__ w2s)
{
    int blk = blockIdx.x;
    if (blk < TRT_TILES) {
        __shared__ float t[32][33];
        const float* src; __nv_bfloat16* dst; int Kd, N, tile;
        if (blk < 6144) {
            int l = blk / 3072; tile = blk % 3072;
            src = wq + (size_t)l*DD*3*DD; dst = g_wt + WT_QKV + (size_t)l*3*DD*DD;
            Kd = DD; N = 3*DD;
        } else if (blk < 8192) {
            int r = blk - 6144; int l = r / 1024; tile = r % 1024;
            src = wo + (size_t)l*DD*DD; dst = g_wt + WT_O + (size_t)l*DD*DD;
            Kd = DD; N = DD;
        } else if (blk < 16384) {
            int r = blk - 8192; int l = r / 4096; tile = r % 4096;
            src = w1s + (size_t)l*DD*FF; dst = g_wt + WT_W1 + (size_t)l*DD*FF;
            Kd = DD; N = FF;
        } else {
            int r = blk - 16384; int l = r / 4096; tile = r % 4096;
            src = w2s + (size_t)l*FF*DD; dst = g_wt + WT_W2 + (size_t)l*FF*DD;
            Kd = FF; N = DD;
        }
        int ntn = N >> 5;
        int k0 = (tile / ntn) << 5, n0 = (tile % ntn) << 5;
        int tx = threadIdx.x & 31, ty = threadIdx.x >> 5;
#pragma unroll
        for (int i = 0; i < 4; i++)
            t[ty + 8*i][tx] = src[(size_t)(k0 + ty + 8*i) * N + n0 + tx];
        __syncthreads();
#pragma unroll
        for (int i = 0; i < 4; i++)
            dst[(size_t)(n0 + ty + 8*i) * Kd + k0 + tx] = __float2bfloat16_rn(t[tx][ty + 8*i]);
    } else {
        int row  = (blk - TRT_TILES) * 8 + (threadIdx.x >> 5);
        int lane = threadIdx.x & 31;
        const float4* xr = (const float4*)(x + (size_t)row * DD);
        const float4* wv = (const float4*)wr;
        float s = 0.f;
#pragma unroll
        for (int i = 0; i < 8; i++) {
            int c = lane + i * 32;
            float4 a = xr[c], b = wv[c];
            s += a.x*b.x + a.y*b.y + a.z*b.z + a.w*b.w;
        }
#pragma unroll
        for (int o = 16; o; o >>= 1) s += __shfl_xor_sync(0xffffffffu, s, o);
        if (!lane) g_logits[row] = s + br[0];
    }
}

// ---------------- exact top-K via radix select + scan (also builds inverse map) ----------------
__global__ void topk_kernel() {
    __shared__ unsigned key[TT];
    __shared__ int s_cnt;
    __shared__ int s_scan[1024];
    int b = blockIdx.x, tid = threadIdx.x;

    for (int t = tid; t < TT; t += 1024) {
        unsigned u = __float_as_uint(g_logits[b*TT + t]);
        u = (u & 0x80000000u) ? ~u : (u | 0x80000000u);
        key[t] = u;
    }
    __syncthreads();

    unsigned prefix = 0; int needed = KK;
    for (int bit = 31; bit >= 0; --bit) {
        if (!tid) s_cnt = 0;
        __syncthreads();
        unsigned cand = prefix | (1u << bit);
        unsigned mask = ~((1u << bit) - 1u);
        int loc = 0;
        for (int t = tid; t < TT; t += 1024) loc += ((key[t] & mask) == cand);
#pragma unroll
        for (int o = 16; o; o >>= 1) loc += __shfl_xor_sync(0xffffffffu, loc, o);
        if ((tid & 31) == 0) atomicAdd(&s_cnt, loc);
        __syncthreads();
        int c = s_cnt;
        if (needed <= c) prefix = cand; else needed -= c;
        __syncthreads();
    }
    int base = tid * 4;
    int vals[4]; int run = 0;
#pragma unroll
    for (int i = 0; i < 4; i++) {
        unsigned k2 = key[base + i];
        int gt = (k2 > prefix), eq = (k2 == prefix);
        vals[i] = run;
        run += (gt << 16) | eq;
    }
    s_scan[tid] = run;
    __syncthreads();
    for (int off = 1; off < 1024; off <<= 1) {
        int v = (tid >= off) ? s_scan[tid - off] : 0;
        __syncthreads();
        s_scan[tid] += v;
        __syncthreads();
    }
    int excl = tid ? s_scan[tid - 1] : 0;
#pragma unroll
    for (int i = 0; i < 4; i++) {
        int t = base + i;
        unsigned k2 = key[t];
        int pre = excl + vals[i];
        int gtB = pre >> 16, eqB = pre & 0xFFFF;
        bool sel = (k2 > prefix) || (k2 == prefix && eqB < needed);
        int pos = gtB + min(eqB, needed);
        g_pos[b*TT + t] = sel ? pos : -1;
        if (sel) {
            g_idx[b*KK + pos] = t;
            float lg = g_logits[b*TT + t];
            g_gate[b*KK + pos] = 1.f / (1.f + expf(-lg));
        }
    }
}

// ---------------- fused gather + layer-0 ln1 (bf16 out) ----------------
__global__ void gather_ln_kernel(const float* __restrict__ x,
                                 const float* __restrict__ scale,
                                 const float* __restrict__ bias) {
    int row = blockIdx.x, tid = threadIdx.x;
    int b = row / KK;
    int t = g_idx[row];
    float4 v = ((const float4*)(x + ((size_t)b*TT + t) * DD))[tid];
    ((float4*)(g_h + (size_t)row * DD))[tid] = v;

    float s  = v.x + v.y + v.z + v.w;
    float sq = v.x*v.x + v.y*v.y + v.z*v.z + v.w*v.w;
#pragma unroll
    for (int o = 16; o; o >>= 1) {
        s  += __shfl_xor_sync(0xffffffffu, s, o);
        sq += __shfl_xor_sync(0xffffffffu, sq, o);
    }
    __shared__ float ss[8], sq2[8];
    if ((tid & 31) == 0) { ss[tid >> 5] = s; sq2[tid >> 5] = sq; }
    __syncthreads();
    float S = 0.f, SQ = 0.f;
#pragma unroll
    for (int i = 0; i < 8; i++) { S += ss[i]; SQ += sq2[i]; }
    float mean = S * (1.f / DD);
    float var  = SQ * (1.f / DD) - mean * mean;
    float inv  = rsqrtf(var + 1e-5f);
    float4 sc = ((const float4*)scale)[tid];
    float4 bi = ((const float4*)bias)[tid];
    __nv_bfloat162 p0 = __floats2bfloat162_rn((v.x - mean) * inv * sc.x + bi.x,
                                              (v.y - mean) * inv * sc.y + bi.y);
    __nv_bfloat162 p1 = __floats2bfloat162_rn((v.z - mean) * inv * sc.z + bi.z,
                                              (v.w - mean) * inv * sc.w + bi.w);
    uint2 pk;
    pk.x = *reinterpret_cast<uint32_t*>(&p0);
    pk.y = *reinterpret_cast<uint32_t*>(&p1);
    ((uint2*)(g_a + (size_t)row * DD))[tid] = pk;
}

// ---------------- layernorm (fp32 in -> bf16 out) ----------------
__global__ void ln_kernel(const float* __restrict__ in, const float* __restrict__ scale,
                          const float* __restrict__ bias, __nv_bfloat16* __restrict__ out) {
    int row = blockIdx.x, tid = threadIdx.x;
    float4 v = ((const float4*)(in + (size_t)row * DD))[tid];
    float s  = v.x + v.y + v.z + v.w;
    float sq = v.x*v.x + v.y*v.y + v.z*v.z + v.w*v.w;
#pragma unroll
    for (int o = 16; o; o >>= 1) {
        s  += __shfl_xor_sync(0xffffffffu, s, o);
        sq += __shfl_xor_sync(0xffffffffu, sq, o);
    }
    __shared__ float ss[8], sq2[8];
    if ((tid & 31) == 0) { ss[tid >> 5] = s; sq2[tid >> 5] = sq; }
    __syncthreads();
    float S = 0.f, SQ = 0.f;
#pragma unroll
    for (int i = 0; i < 8; i++) { S += ss[i]; SQ += sq2[i]; }
    float mean = S * (1.f / DD);
    float var  = SQ * (1.f / DD) - mean * mean;
    float inv  = rsqrtf(var + 1e-5f);
    float4 sc = ((const float4*)scale)[tid];
    float4 bi = ((const float4*)bias)[tid];
    __nv_bfloat162 p0 = __floats2bfloat162_rn((v.x - mean) * inv * sc.x + bi.x,
                                              (v.y - mean) * inv * sc.y + bi.y);
    __nv_bfloat162 p1 = __floats2bfloat162_rn((v.z - mean) * inv * sc.z + bi.z,
                                              (v.w - mean) * inv * sc.w + bi.w);
    uint2 pk;
    pk.x = *reinterpret_cast<uint32_t*>(&p0);
    pk.y = *reinterpret_cast<uint32_t*>(&p1);
    ((uint2*)(out + (size_t)row * DD))[tid] = pk;
}

// ---------------- single-pass output: copy + gated scatter-add + tail ----------------
#define OUT_MAIN_BLOCKS 8192   // BB*TT*DD/4/256
__global__ void out_kernel(const float* __restrict__ x, float* __restrict__ out) {
    int blk = blockIdx.x;
    if (blk < OUT_MAIN_BLOCKS) {
        size_t i = (size_t)blk * 256 + threadIdx.x;   // float4 index
        int row = (int)(i >> 8);
        int b = row >> 12;
        int t = row & (TT - 1);
        float4 v = ((const float4*)x)[i];
        int pos = g_pos[b*TT + t];
        if (pos >= 0) {
            float gg = g_gate[b*KK + pos];
            float4 hv = ((const float4*)(g_h + ((size_t)b*KK + pos) * DD))[i & 255];
            v.x += gg*hv.x; v.y += gg*hv.y; v.z += gg*hv.z; v.w += gg*hv.w;
        }
        ((float4*)out)[i] = v;
    } else {
        int i = (blk - OUT_MAIN_BLOCKS) * 256 + threadIdx.x;
        size_t base = (size_t)BB * TT * DD;
        if (i < BB*KK) out[base + i] = (float)g_idx[i];
        if (i < BB*TT) out[base + BB*KK + i] = g_logits[i];
    }
}

// ---------------- flash attention: mma.sync tf32, causal, 64x64 tiles ----------------
#define AQ 4352        // 64*68
#define AK 4352
#define AP 4352
#define AV 4608        // 64*72
#define ATTN2_SMEM ((AQ + 2*AK + AP + 2*AV)*4)

__global__ __launch_bounds__(128) void attn_mma_kernel() {
    extern __shared__ __align__(16) float sm[];
    float* Qs = sm;
    float* Ks = sm + AQ;                 // 2 stages
    float* Ps = sm + AQ + 2*AK;
    float* Vs = sm + AQ + 2*AK + AP;     // 2 stages
    uint32_t q_addr = smem_u32(Qs);
    uint32_t k_addr = smem_u32(Ks);
    uint32_t v_addr = smem_u32(Vs);

    int tid = threadIdx.x;
    int wid = tid >> 5, lane = tid & 31;
    int g = lane >> 2, tig = lane & 3;
    int qb = gridDim.x - 1 - blockIdx.x;      // heavy tiles first
    int bh = blockIdx.y;
    int b = bh >> 4, h = bh & 15;
    const float* qkv = g_qkv + (size_t)b * KK * 3 * DD + h * DHD;  // row stride 3*DD

    auto load_kv = [&](int s, int jt) {
#pragma unroll
        for (int i = 0; i < 8; i++) {
            int chunk = tid + 128*i;
            int r = chunk >> 4, c4 = chunk & 15;
            const float* src = qkv + (size_t)(jt*64 + r) * (3*DD) + c4*4;
            cpasync16(k_addr + (uint32_t)(s*AK + r*68)*4 + c4*16, src + DD);
            cpasync16(v_addr + (uint32_t)(s*AV + r*72)*4 + c4*16, src + 2*DD);
        }
        cp_commit();
    };

#pragma unroll
    for (int i = 0; i < 8; i++) {
        int chunk = tid + 128*i;
        int r = chunk >> 4, c4 = chunk & 15;
        cpasync16(q_addr + (uint32_t)(r*68)*4 + c4*16,
                  qkv + (size_t)(qb*64 + r) * (3*DD) + c4*4);
    }
    load_kv(0, 0);

    float mrow[2] = {-3.0e38f, -3.0e38f};
    float lrow[2] = {0.f, 0.f};
    float accO[8][4];
#pragma unroll
    for (int ni = 0; ni < 8; ni++)
#pragma unroll
        for (int c = 0; c < 4; c++) accO[ni][c] = 0.f;

    int qrow = wid*16 + g;

    for (int jt = 0; jt <= qb; jt++) {
        if (jt < qb) load_kv((jt+1) & 1, jt+1);
        if (jt < qb) asm volatile("cp.async.wait_group 1;" ::: "memory");
        else         asm volatile("cp.async.wait_group 0;" ::: "memory");
        __syncthreads();

        const float* ks = Ks + (jt & 1)*AK;
        const float* vs = Vs + (jt & 1)*AV;

        float accS[8][4];
#pragma unroll
        for (int ni = 0; ni < 8; ni++)
#pragma unroll
            for (int c = 0; c < 4; c++) accS[ni][c] = 0.f;
#pragma unroll
        for (int k8 = 0; k8 < 8; k8++) {
            int k = k8*8;
            float af[4];
            af[0] = Qs[(qrow)*68 + k + tig];
            af[1] = Qs[(qrow+8)*68 + k + tig];
            af[2] = Qs[(qrow)*68 + k + tig + 4];
            af[3] = Qs[(qrow+8)*68 + k + tig + 4];
#pragma unroll
            for (int ni = 0; ni < 8; ni++) {
                float bf[2];
                bf[0] = ks[(8*ni + g)*68 + k + tig];
                bf[1] = ks[(8*ni + g)*68 + k + tig + 4];
                mma8(accS[ni], af, bf);
            }
        }

        bool diag = (jt == qb);
#pragma unroll
        for (int ni = 0; ni < 8; ni++)
#pragma unroll
            for (int c = 0; c < 4; c++) {
                float s = accS[ni][c] * 0.125f;
                if (diag) {
                    int kg = 8*ni + 2*tig + (c & 1);
                    int qg = wid*16 + g + 8*(c >> 1);
                    if (kg > qg) s = -3.0e38f;
                }
                accS[ni][c] = s;
            }

#pragma unroll
        for (int r = 0; r < 2; r++) {
            float rm = -3.0e38f;
#pragma unroll
            for (int ni = 0; ni < 8; ni++)
                rm = fmaxf(rm, fmaxf(accS[ni][2*r], accS[ni][2*r+1]));
            rm = fmaxf(rm, __shfl_xor_sync(0xffffffffu, rm, 1));
            rm = fmaxf(rm, __shfl_xor_sync(0xffffffffu, rm, 2));
            float mn = fmaxf(mrow[r], rm);
            float corr = __expf(mrow[r] - mn);
            mrow[r] = mn;
            float rs = 0.f;
#pragma unroll
            for (int ni = 0; ni < 8; ni++) {
                float p0 = __expf(accS[ni][2*r]   - mn);
                float p1 = __expf(accS[ni][2*r+1] - mn);
                rs += p0 + p1;
                accS[ni][2*r]   = tf32rn(p0);
                accS[ni][2*r+1] = tf32rn(p1);
            }
            rs += __shfl_xor_sync(0xffffffffu, rs, 1);
            rs += __shfl_xor_sync(0xffffffffu, rs, 2);
            lrow[r] = lrow[r] * corr + rs;
#pragma unroll
            for (int ni = 0; ni < 8; ni++) {
                accO[ni][2*r]   *= corr;
                accO[ni][2*r+1] *= corr;
            }
        }

#pragma unroll
        for (int ni = 0; ni < 8; ni++) {
            float2 p0; p0.x = accS[ni][0]; p0.y = accS[ni][1];
            float2 p1; p1.x = accS[ni][2]; p1.y = accS[ni][3];
            *(float2*)&Ps[(qrow)*68 + 8*ni + 2*tig]   = p0;
            *(float2*)&Ps[(qrow+8)*68 + 8*ni + 2*tig] = p1;
        }
        __syncwarp();

#pragma unroll
        for (int k8 = 0; k8 < 8; k8++) {
            int k = k8*8;
            float af[4];
            af[0] = Ps[(qrow)*68 + k + tig];
            af[1] = Ps[(qrow+8)*68 + k + tig];
            af[2] = Ps[(qrow)*68 + k + tig + 4];
            af[3] = Ps[(qrow+8)*68 + k + tig + 4];
#pragma unroll
            for (int ni = 0; ni < 8; ni++) {
                float bf[2];
                bf[0] = vs[(k + tig)*72 + 8*ni + g];
                bf[1] = vs[(k + tig + 4)*72 + 8*ni + g];
                mma8(accO[ni], af, bf);
            }
        }
        __syncthreads();
    }

    // normalize + write bf16 (feeds o-proj GEMM)
    __nv_bfloat16* op = g_attn + (size_t)b * KK * DD + h * DHD;
#pragma unroll
    for (int r = 0; r < 2; r++) {
        float inv = 1.f / lrow[r];
        int row = qb*64 + wid*16 + g + 8*r;
#pragma unroll
        for (int ni = 0; ni < 8; ni++) {
            __nv_bfloat162 ov = __floats2bfloat162_rn(accO[ni][2*r]   * inv,
                                                      accO[ni][2*r+1] * inv);
            *(__nv_bfloat162*)(op + (size_t)row * DD + 8*ni + 2*tig) = ov;
        }
    }
}

// ---------------- launch ----------------
extern "C" void kernel_launch(void* const* d_in, const int* in_sizes, int n_in,
                              void* d_out, int out_size) {
    const float* x        = (const float*)d_in[0];
    const float* w_router = (const float*)d_in[1];
    const float* b_router = (const float*)d_in[2];
    const float* ln1_s    = (const float*)d_in[3];
    const float* ln1_b    = (const float*)d_in[4];
    const float* w_qkv    = (const float*)d_in[5];
    const float* b_qkv    = (const float*)d_in[6];
    const float* w_o      = (const float*)d_in[7];
    const float* b_o      = (const float*)d_in[8];
    const float* ln2_s    = (const float*)d_in[9];
    const float* ln2_b    = (const float*)d_in[10];
    const float* w1       = (const float*)d_in[11];
    const float* b1       = (const float*)d_in[12];
    const float* w2       = (const float*)d_in[13];
    const float* b2       = (const float*)d_in[14];
    float* out = (float*)d_out;

    float *p_h, *p_qkv;
    __nv_bfloat16 *p_a, *p_attn, *p_ffn, *p_wt;
    cudaGetSymbolAddress((void**)&p_h,    g_h);
    cudaGetSymbolAddress((void**)&p_a,    g_a);
    cudaGetSymbolAddress((void**)&p_qkv,  g_qkv);
    cudaGetSymbolAddress((void**)&p_attn, g_attn);
    cudaGetSymbolAddress((void**)&p_ffn,  g_ffn);
    cudaGetSymbolAddress((void**)&p_wt,   g_wt);

    cudaFuncSetAttribute(attn_mma_kernel, cudaFuncAttributeMaxDynamicSharedMemorySize,
                         ATTN2_SMEM);
    cudaFuncSetAttribute(mma_gemm<1>, cudaFuncAttributeMaxDynamicSharedMemorySize, GEMM_SMEM);
    cudaFuncSetAttribute(mma_gemm<2>, cudaFuncAttributeMaxDynamicSharedMemorySize, GEMM_SMEM);
    cudaFuncSetAttribute(mma_gemm<3>, cudaFuncAttributeMaxDynamicSharedMemorySize, GEMM_SMEM);

    // 1: weight transpose + bf16 round + router (fused)
    trans_router_kernel<<<TRT_TILES + BB*TT/8, 256>>>(
        x, w_router, b_router, w_qkv, w_o, w1, w2);
    // 2: exact top-K
    topk_kernel<<<BB, 1024>>>();
    // 3: gather + layer-0 ln1
    gather_ln_kernel<<<MROWS, 256>>>(x, ln1_s, ln1_b);

    for (int l = 0; l < LL; l++) {
        if (l > 0)
            ln_kernel<<<MROWS, 256>>>(p_h, ln1_s + l*DD, ln1_b + l*DD, p_a);
        // 4 (for l=0): qkv GEMM -> profiled launch
        mma_gemm<3><<<dim3(3*DD/NTB, MROWS/MT), GEMM_THREADS, GEMM_SMEM>>>(
            p_a, p_wt + WT_QKV + (size_t)l*3*DD*DD, b_qkv + (size_t)l*3*DD, nullptr,
            p_qkv, DD, 3*DD);
        attn_mma_kernel<<<dim3(KK/64, BB*HH), 128, ATTN2_SMEM>>>();
        mma_gemm<2><<<dim3(DD/NTB, MROWS/MT), GEMM_THREADS, GEMM_SMEM>>>(
            p_attn, p_wt + WT_O + (size_t)l*DD*DD, b_o + (size_t)l*DD, p_h,
            p_h, DD, DD);
        ln_kernel<<<MROWS, 256>>>(p_h, ln2_s + l*DD, ln2_b + l*DD, p_a);
        mma_gemm<1><<<dim3(FF/NTB, MROWS/MT), GEMM_THREADS, GEMM_SMEM>>>(
            p_a, p_wt + WT_W1 + (size_t)l*FF*DD, b1 + (size_t)l*FF, nullptr,
            (float*)p_ffn, DD, FF);
        mma_gemm<2><<<dim3(DD/NTB, MROWS/MT), GEMM_THREADS, GEMM_SMEM>>>(
            p_ffn, p_wt + WT_W2 + (size_t)l*DD*FF, b2 + (size_t)l*DD, p_h,
            p_h, FF, DD);
    }

    long long full = (long long)BB*TT*DD + (long long)BB*KK + (long long)BB*TT;
    int tail_blocks = ((long long)out_size >= full) ? 32 : 0;
    out_kernel<<<OUT_MAIN_BLOCKS + tail_blocks, 256>>>(x, out);
}

// round 17
// speedup vs baseline: 1.6548x; 1.2296x over previous
#include <cuda_runtime.h>
#include <cuda_bf16.h>
#include <math.h>
#include <stdint.h>

#define BB 2
#define TT 4096
#define DD 1024
#define LL 2
#define HH 16
#define FF 4096
#define KK 2048
#define DHD 64
#define MROWS (BB*KK)   // 4096 (batch folded into M)

// ---------------- scratch (static device globals; no allocations) ----------------
__device__ float g_logits[BB*TT];
__device__ int   g_idx[BB*KK];
__device__ int   g_pos[BB*TT];     // token -> k-position (or -1)
__device__ float g_gate[BB*KK];
__device__ float g_h[BB*KK*DD];
__device__ __nv_bfloat16 g_a[BB*KK*DD];
__device__ __nv_bfloat16 g_qkv[BB*KK*3*DD];
__device__ __nv_bfloat16 g_attn[BB*KK*DD];
__device__ __nv_bfloat16 g_ffn[(size_t)BB*KK*FF];

// transposed ([N][K] k-contiguous) bf16 weights
#define WT_QKV 0
#define WT_O   (LL*DD*3*DD)
#define WT_W1  (WT_O + LL*DD*DD)
#define WT_W2  (WT_W1 + LL*DD*FF)
#define WT_TOT (WT_W2 + LL*FF*DD)
__device__ __nv_bfloat16 g_wt[WT_TOT];

// ---------------- helpers ----------------
__device__ __forceinline__ uint32_t smem_u32(const void* p) {
    uint32_t a;
    asm("{ .reg .u64 t; cvta.to.shared.u64 t, %1; cvt.u32.u64 %0, t; }" : "=r"(a) : "l"(p));
    return a;
}
__device__ __forceinline__ float tf32rn(float x) {
    uint32_t u;
    asm("cvt.rna.tf32.f32 %0, %1;" : "=r"(u) : "f"(x));
    return __uint_as_float(u);
}
__device__ __forceinline__ void cpasync16(uint32_t dst, const void* src) {
    asm volatile("cp.async.cg.shared.global [%0], [%1], 16;" :: "r"(dst), "l"(src) : "memory");
}
__device__ __forceinline__ void cp_commit() {
    asm volatile("cp.async.commit_group;" ::: "memory");
}
__device__ __forceinline__ void mbar_init(uint32_t a, uint32_t cnt) {
    asm volatile("mbarrier.init.shared.b64 [%0], %1;" :: "r"(a), "r"(cnt) : "memory");
}
__device__ __forceinline__ void mbar_arrive(uint32_t a) {
    asm volatile("mbarrier.arrive.shared.b64 _, [%0];" :: "r"(a) : "memory");
}
__device__ __forceinline__ void mbar_wait(uint32_t a, uint32_t parity) {
    asm volatile(
        "{\n\t.reg .pred P;\n\tWL%=:\n\t"
        "mbarrier.try_wait.parity.acquire.cta.shared::cta.b64 P, [%0], %1;\n\t"
        "@P bra WD%=;\n\tbra WL%=;\n\tWD%=:\n\t}"
        :: "r"(a), "r"(parity) : "memory");
}
__device__ __forceinline__ void cpasync_arrive_noinc(uint32_t mbar) {
    asm volatile("cp.async.mbarrier.arrive.noinc.shared.b64 [%0];" :: "r"(mbar) : "memory");
}
__device__ __forceinline__ void ldsm4(uint32_t& r0, uint32_t& r1, uint32_t& r2, uint32_t& r3,
                                      uint32_t addr) {
    asm volatile("ldmatrix.sync.aligned.m8n8.x4.shared.b16 {%0,%1,%2,%3}, [%4];"
        : "=r"(r0), "=r"(r1), "=r"(r2), "=r"(r3) : "r"(addr));
}
__device__ __forceinline__ void ldsm4t(uint32_t& r0, uint32_t& r1, uint32_t& r2, uint32_t& r3,
                                       uint32_t addr) {
    asm volatile("ldmatrix.sync.aligned.m8n8.x4.trans.shared.b16 {%0,%1,%2,%3}, [%4];"
        : "=r"(r0), "=r"(r1), "=r"(r2), "=r"(r3) : "r"(addr));
}
__device__ __forceinline__ void mma16(float* d, const uint32_t* a, const uint32_t* b) {
    asm volatile("mma.sync.aligned.m16n8k16.row.col.f32.bf16.bf16.f32 "
        "{%0,%1,%2,%3}, {%4,%5,%6,%7}, {%8,%9}, {%0,%1,%2,%3};"
        : "+f"(d[0]), "+f"(d[1]), "+f"(d[2]), "+f"(d[3])
        : "r"(a[0]), "r"(a[1]), "r"(a[2]), "r"(a[3]), "r"(b[0]), "r"(b[1]));
}

__device__ __forceinline__ float gelu_f(float x) {
    float x3 = x * x * x;
    float t = tanhf(0.7978845608028654f * (x + 0.044715f * x3));
    return 0.5f * x * (1.f + t);
}

// ---------------- warp-specialized bf16 m16n8k16 GEMM ----------------
// C = A(M x Kd) @ Wt^T + bias.  A: [M][Kd] bf16; Wt: [Ntot][Kd] bf16.
// CTA tile 128x64. 8 consumer warps (32x32 tiles) + 2 producer warps.
// 4-stage cp.async ring (K-chunk 64), mbarrier full/done; no CTA barrier in mainloop.
#define MT 128
#define NTB 64
#define KCHB 64                          // bf16 k elements per stage
#define TSTB 144                         // row stride in BYTES (72 bf16)
#define STG_BYTES ((MT+NTB)*TSTB)        // 27648
#define NSTG 4
#define GEMM_SMEM (NSTG*STG_BYTES)       // 110592 -> 2 CTAs/SM
#define GEMM_THREADS 320                 // 256 consumer + 64 producer

// EPI: 1 = bias+gelu -> bf16 out, 2 = bias+residual (fp32), 4 = bias -> bf16 out
template <int EPI>
__global__ __launch_bounds__(GEMM_THREADS, 2) void mma_gemm(
    const __nv_bfloat16* __restrict__ A, const __nv_bfloat16* __restrict__ Wt,
    const float* __restrict__ bias, const float* __restrict__ res,
    float* __restrict__ C, int Kd, int Ntot)
{
    extern __shared__ __align__(16) char smc[];
    __shared__ __align__(8) uint64_t mbars[2*NSTG];   // full[s], done[s]
    uint32_t sbase = smem_u32(smc);
    uint32_t barb  = smem_u32(mbars);

    int tid = threadIdx.x;
    int bn = blockIdx.x, bm = blockIdx.y;
    int wid = tid >> 5, lane = tid & 31;
    int nk = Kd / KCHB;

    if (tid == 0) {
        for (int s = 0; s < NSTG; s++) {
            mbar_init(barb + 16*s, 64);      // full: 64 producer arrivals (noinc)
            mbar_init(barb + 16*s + 8, 8);   // done: 8 consumer-warp arrivals
        }
    }
    __syncthreads();

    if (wid >= 8) {
        // ---- producers: 64 threads fill stages (192 rows x 128 B) ----
        int t = tid - 256;
        const __nv_bfloat16* Ag = A + (size_t)(bm*MT) * Kd;
        const __nv_bfloat16* Bg = Wt + (size_t)(bn*NTB) * Kd;
        int s = 0, ph = 1;
        for (int kt = 0; kt < nk; kt++) {
            mbar_wait(barb + 16*s + 8, ph);
            uint32_t stb = sbase + (uint32_t)(s*STG_BYTES);
            const __nv_bfloat16* Ak = Ag + kt*KCHB;
            const __nv_bfloat16* Bk = Bg + kt*KCHB;
#pragma unroll
            for (int i = 0; i < 24; i++) {
                int chunk = t + 64*i;
                int row = chunk >> 3, seg = chunk & 7;
                const __nv_bfloat16* src = (row < MT) ? (Ak + (size_t)row*Kd + seg*8)
                                                      : (Bk + (size_t)(row-MT)*Kd + seg*8);
                cpasync16(stb + (uint32_t)(row*TSTB + seg*16), src);
            }
            cpasync_arrive_noinc(barb + 16*s);
            if (++s == NSTG) { s = 0; ph ^= 1; }
        }
        return;
    }

    // ---- consumers: 8 warps, warp tile 32(M) x 32(N), k16 steps ----
    int wm = wid & 3, wn = wid >> 2;
    int g = lane >> 2, tig = lane & 3;
    int lj = lane & 7, lsub = lane >> 3;
    uint32_t a_lane_off = (uint32_t)(((lsub & 1)*8 + lj)*TSTB + (lsub >> 1)*16);
    uint32_t b_lane_off = (uint32_t)((((lsub >> 1)&1)*8 + lj)*TSTB + (lsub & 1)*16);

    float acc[2][4][4];
#pragma unroll
    for (int mi = 0; mi < 2; mi++)
#pragma unroll
        for (int ni = 0; ni < 4; ni++)
#pragma unroll
            for (int c = 0; c < 4; c++) acc[mi][ni][c] = 0.f;

    int s = 0, ph = 0;
    for (int kt = 0; kt < nk; kt++) {
        mbar_wait(barb + 16*s, ph);
        uint32_t a_tile = sbase + (uint32_t)(s*STG_BYTES) + (uint32_t)(wm*32*TSTB) + a_lane_off;
        uint32_t b_tile = sbase + (uint32_t)(s*STG_BYTES) + (uint32_t)((MT + wn*32)*TSTB) + b_lane_off;
#pragma unroll
        for (int ks = 0; ks < 4; ks++) {
            uint32_t kb = ks*32;             // 16 bf16 = 32 bytes per step
            uint32_t af[2][4];
#pragma unroll
            for (int mi = 0; mi < 2; mi++)
                ldsm4(af[mi][0], af[mi][1], af[mi][2], af[mi][3],
                      a_tile + (uint32_t)(mi*16*TSTB) + kb);
            uint32_t bf[4][2];
#pragma unroll
            for (int p = 0; p < 2; p++)
                ldsm4(bf[2*p][0], bf[2*p][1], bf[2*p+1][0], bf[2*p+1][1],
                      b_tile + (uint32_t)(p*16*TSTB) + kb);
#pragma unroll
            for (int mi = 0; mi < 2; mi++)
#pragma unroll
                for (int ni = 0; ni < 4; ni++)
                    mma16(acc[mi][ni], af[mi], bf[ni]);
        }
        if (lane == 0) mbar_arrive(barb + 16*s + 8);
        if (++s == NSTG) { s = 0; ph ^= 1; }
    }

    // ---- epilogue ----
#pragma unroll
    for (int mi = 0; mi < 2; mi++) {
        int r0 = bm*MT + wm*32 + mi*16 + g;
#pragma unroll
        for (int ni = 0; ni < 4; ni++) {
            int col = bn*NTB + wn*32 + ni*8 + tig*2;
            float2 bv = *(const float2*)(bias + col);
#pragma unroll
            for (int hrow = 0; hrow < 2; hrow++) {
                int r = r0 + hrow*8;
                float o0 = acc[mi][ni][hrow*2+0] + bv.x;
                float o1 = acc[mi][ni][hrow*2+1] + bv.y;
                if (EPI == 1 || EPI == 4) {
                    if (EPI == 1) { o0 = gelu_f(o0); o1 = gelu_f(o1); }
                    __nv_bfloat162 pv = __floats2bfloat162_rn(o0, o1);
                    *(__nv_bfloat162*)((__nv_bfloat16*)C + (size_t)r * Ntot + col) = pv;
                } else {
                    if (EPI == 2) {
                        float2 rv = *(const float2*)(res + (size_t)r * Ntot + col);
                        o0 += rv.x; o1 += rv.y;
                    }
                    float2 ov; ov.x = o0; ov.y = o1;
                    *(float2*)(C + (size_t)r * Ntot + col) = ov;
                }
            }
        }
    }
}

// ---------------- fused: weight transpose([K][N]->[N][K]) + bf16 round + router ----------------
#define TRT_TILES 24576
__global__ void trans_router_kernel(
    const float* __restrict__ x, const float* __restrict__ wr, const float* __restrict__ br,
    const float* __restrict__ wq, const float* __restrict__ wo,
    const float* __restrict__ w1s, const float* __restrict__ w2s)
{
    int blk = blockIdx.x;
    if (blk < TRT_TILES) {
        __shared__ float t[32][33];
        const float* src; __nv_bfloat16* dst; int Kd, N, tile;
        if (blk < 6144) {
            int l = blk / 3072; tile = blk % 3072;
            src = wq + (size_t)l*DD*3*DD; dst = g_wt + WT_QKV + (size_t)l*3*DD*DD;
            Kd = DD; N = 3*DD;
        } else if (blk < 8192) {
            int r = blk - 6144; int l = r / 1024; tile = r % 1024;
            src = wo + (size_t)l*DD*DD; dst = g_wt + WT_O + (size_t)l*DD*DD;
            Kd = DD; N = DD;
        } else if (blk < 16384) {
            int r = blk - 8192; int l = r / 4096; tile = r % 4096;
            src = w1s + (size_t)l*DD*FF; dst = g_wt + WT_W1 + (size_t)l*DD*FF;
            Kd = DD; N = FF;
        } else {
            int r = blk - 16384; int l = r / 4096; tile = r % 4096;
            src = w2s + (size_t)l*FF*DD; dst = g_wt + WT_W2 + (size_t)l*FF*DD;
            Kd = FF; N = DD;
        }
        int ntn = N >> 5;
        int k0 = (tile / ntn) << 5, n0 = (tile % ntn) << 5;
        int tx = threadIdx.x & 31, ty = threadIdx.x >> 5;
#pragma unroll
        for (int i = 0; i < 4; i++)
            t[ty + 8*i][tx] = src[(size_t)(k0 + ty + 8*i) * N + n0 + tx];
        __syncthreads();
#pragma unroll
        for (int i = 0; i < 4; i++)
            dst[(size_t)(n0 + ty + 8*i) * Kd + k0 + tx] = __float2bfloat16_rn(t[tx][ty + 8*i]);
    } else {
        int row  = (blk - TRT_TILES) * 8 + (threadIdx.x >> 5);
        int lane = threadIdx.x & 31;
        const float4* xr = (const float4*)(x + (size_t)row * DD);
        const float4* wv = (const float4*)wr;
        float s = 0.f;
#pragma unroll
        for (int i = 0; i < 8; i++) {
            int c = lane + i * 32;
            float4 a = xr[c], b = wv[c];
            s += a.x*b.x + a.y*b.y + a.z*b.z + a.w*b.w;
        }
#pragma unroll
        for (int o = 16; o; o >>= 1) s += __shfl_xor_sync(0xffffffffu, s, o);
        if (!lane) g_logits[row] = s + br[0];
    }
}

// ---------------- exact top-K via radix select + scan (also builds inverse map) ----------------
__global__ void topk_kernel() {
    __shared__ unsigned key[TT];
    __shared__ int s_cnt;
    __shared__ int s_scan[1024];
    int b = blockIdx.x, tid = threadIdx.x;

    for (int t = tid; t < TT; t += 1024) {
        unsigned u = __float_as_uint(g_logits[b*TT + t]);
        u = (u & 0x80000000u) ? ~u : (u | 0x80000000u);
        key[t] = u;
    }
    __syncthreads();

    unsigned prefix = 0; int needed = KK;
    for (int bit = 31; bit >= 0; --bit) {
        if (!tid) s_cnt = 0;
        __syncthreads();
        unsigned cand = prefix | (1u << bit);
        unsigned mask = ~((1u << bit) - 1u);
        int loc = 0;
        for (int t = tid; t < TT; t += 1024) loc += ((key[t] & mask) == cand);
#pragma unroll
        for (int o = 16; o; o >>= 1) loc += __shfl_xor_sync(0xffffffffu, loc, o);
        if ((tid & 31) == 0) atomicAdd(&s_cnt, loc);
        __syncthreads();
        int c = s_cnt;
        if (needed <= c) prefix = cand; else needed -= c;
        __syncthreads();
    }
    int base = tid * 4;
    int vals[4]; int run = 0;
#pragma unroll
    for (int i = 0; i < 4; i++) {
        unsigned k2 = key[base + i];
        int gt = (k2 > prefix), eq = (k2 == prefix);
        vals[i] = run;
        run += (gt << 16) | eq;
    }
    s_scan[tid] = run;
    __syncthreads();
    for (int off = 1; off < 1024; off <<= 1) {
        int v = (tid >= off) ? s_scan[tid - off] : 0;
        __syncthreads();
        s_scan[tid] += v;
        __syncthreads();
    }
    int excl = tid ? s_scan[tid - 1] : 0;
#pragma unroll
    for (int i = 0; i < 4; i++) {
        int t = base + i;
        unsigned k2 = key[t];
        int pre = excl + vals[i];
        int gtB = pre >> 16, eqB = pre & 0xFFFF;
        bool sel = (k2 > prefix) || (k2 == prefix && eqB < needed);
        int pos = gtB + min(eqB, needed);
        g_pos[b*TT + t] = sel ? pos : -1;
        if (sel) {
            g_idx[b*KK + pos] = t;
            float lg = g_logits[b*TT + t];
            g_gate[b*KK + pos] = 1.f / (1.f + expf(-lg));
        }
    }
}

// ---------------- fused gather + layer-0 ln1 (bf16 out) ----------------
__global__ void gather_ln_kernel(const float* __restrict__ x,
                                 const float* __restrict__ scale,
                                 const float* __restrict__ bias) {
    int row = blockIdx.x, tid = threadIdx.x;
    int b = row / KK;
    int t = g_idx[row];
    float4 v = ((const float4*)(x + ((size_t)b*TT + t) * DD))[tid];
    ((float4*)(g_h + (size_t)row * DD))[tid] = v;

    float s  = v.x + v.y + v.z + v.w;
    float sq = v.x*v.x + v.y*v.y + v.z*v.z + v.w*v.w;
#pragma unroll
    for (int o = 16; o; o >>= 1) {
        s  += __shfl_xor_sync(0xffffffffu, s, o);
        sq += __shfl_xor_sync(0xffffffffu, sq, o);
    }
    __shared__ float ss[8], sq2[8];
    if ((tid & 31) == 0) { ss[tid >> 5] = s; sq2[tid >> 5] = sq; }
    __syncthreads();
    float S = 0.f, SQ = 0.f;
#pragma unroll
    for (int i = 0; i < 8; i++) { S += ss[i]; SQ += sq2[i]; }
    float mean = S * (1.f / DD);
    float var  = SQ * (1.f / DD) - mean * mean;
    float inv  = rsqrtf(var + 1e-5f);
    float4 sc = ((const float4*)scale)[tid];
    float4 bi = ((const float4*)bias)[tid];
    __nv_bfloat162 p0 = __floats2bfloat162_rn((v.x - mean) * inv * sc.x + bi.x,
                                              (v.y - mean) * inv * sc.y + bi.y);
    __nv_bfloat162 p1 = __floats2bfloat162_rn((v.z - mean) * inv * sc.z + bi.z,
                                              (v.w - mean) * inv * sc.w + bi.w);
    uint2 pk;
    pk.x = *reinterpret_cast<uint32_t*>(&p0);
    pk.y = *reinterpret_cast<uint32_t*>(&p1);
    ((uint2*)(g_a + (size_t)row * DD))[tid] = pk;
}

// ---------------- layernorm (fp32 in -> bf16 out) ----------------
__global__ void ln_kernel(const float* __restrict__ in, const float* __restrict__ scale,
                          const float* __restrict__ bias, __nv_bfloat16* __restrict__ out) {
    int row = blockIdx.x, tid = threadIdx.x;
    float4 v = ((const float4*)(in + (size_t)row * DD))[tid];
    float s  = v.x + v.y + v.z + v.w;
    float sq = v.x*v.x + v.y*v.y + v.z*v.z + v.w*v.w;
#pragma unroll
    for (int o = 16; o; o >>= 1) {
        s  += __shfl_xor_sync(0xffffffffu, s, o);
        sq += __shfl_xor_sync(0xffffffffu, sq, o);
    }
    __shared__ float ss[8], sq2[8];
    if ((tid & 31) == 0) { ss[tid >> 5] = s; sq2[tid >> 5] = sq; }
    __syncthreads();
    float S = 0.f, SQ = 0.f;
#pragma unroll
    for (int i = 0; i < 8; i++) { S += ss[i]; SQ += sq2[i]; }
    float mean = S * (1.f / DD);
    float var  = SQ * (1.f / DD) - mean * mean;
    float inv  = rsqrtf(var + 1e-5f);
    float4 sc = ((const float4*)scale)[tid];
    float4 bi = ((const float4*)bias)[tid];
    __nv_bfloat162 p0 = __floats2bfloat162_rn((v.x - mean) * inv * sc.x + bi.x,
                                              (v.y - mean) * inv * sc.y + bi.y);
    __nv_bfloat162 p1 = __floats2bfloat162_rn((v.z - mean) * inv * sc.z + bi.z,
                                              (v.w - mean) * inv * sc.w + bi.w);
    uint2 pk;
    pk.x = *reinterpret_cast<uint32_t*>(&p0);
    pk.y = *reinterpret_cast<uint32_t*>(&p1);
    ((uint2*)(out + (size_t)row * DD))[tid] = pk;
}

// ---------------- single-pass output: copy + gated scatter-add + tail ----------------
#define OUT_MAIN_BLOCKS 8192   // BB*TT*DD/4/256
__global__ void out_kernel(const float* __restrict__ x, float* __restrict__ out) {
    int blk = blockIdx.x;
    if (blk < OUT_MAIN_BLOCKS) {
        size_t i = (size_t)blk * 256 + threadIdx.x;   // float4 index
        int row = (int)(i >> 8);
        int b = row >> 12;
        int t = row & (TT - 1);
        float4 v = ((const float4*)x)[i];
        int pos = g_pos[b*TT + t];
        if (pos >= 0) {
            float gg = g_gate[b*KK + pos];
            float4 hv = ((const float4*)(g_h + ((size_t)b*KK + pos) * DD))[i & 255];
            v.x += gg*hv.x; v.y += gg*hv.y; v.z += gg*hv.z; v.w += gg*hv.w;
        }
        ((float4*)out)[i] = v;
    } else {
        int i = (blk - OUT_MAIN_BLOCKS) * 256 + threadIdx.x;
        size_t base = (size_t)BB * TT * DD;
        if (i < BB*KK) out[base + i] = (float)g_idx[i];
        if (i < BB*TT) out[base + BB*KK + i] = g_logits[i];
    }
}

// ---------------- flash attention: bf16 m16n8k16, causal, 64x64 tiles ----------------
// Q | K(2 stages) | V(2 stages) | P ; all tiles 64 rows x 144 B (72 bf16)
#define ATS 144
#define ATILE_B (64*ATS)                 // 9216
#define ATTN3_SMEM (6*ATILE_B)           // 55296

__global__ __launch_bounds__(128) void attn_mma_kernel() {
    extern __shared__ __align__(16) char smA[];
    uint32_t q_addr = smem_u32(smA);
    uint32_t k_addr = q_addr + ATILE_B;      // + s*ATILE_B
    uint32_t v_addr = q_addr + 3*ATILE_B;    // + s*ATILE_B
    uint32_t p_addr = q_addr + 5*ATILE_B;

    int tid = threadIdx.x;
    int wid = tid >> 5, lane = tid & 31;
    int g = lane >> 2, tig = lane & 3;
    int lj = lane & 7, lsub = lane >> 3;
    int qb = gridDim.x - 1 - blockIdx.x;      // heavy tiles first
    int bh = blockIdx.y;
    int b = bh >> 4, h = bh & 15;
    const __nv_bfloat16* qkv = g_qkv + (size_t)b * KK * 3 * DD + h * DHD;  // row stride 3*DD

    auto load_kv = [&](int s, int jt) {
#pragma unroll
        for (int i = 0; i < 4; i++) {
            int chunk = tid + 128*i;
            int r = chunk >> 3, c8 = chunk & 7;
            const __nv_bfloat16* src = qkv + (size_t)(jt*64 + r) * (3*DD) + c8*8;
            cpasync16(k_addr + (uint32_t)(s*ATILE_B + r*ATS + c8*16), src + DD);
            cpasync16(v_addr + (uint32_t)(s*ATILE_B + r*ATS + c8*16), src + 2*DD);
        }
        cp_commit();
    };

#pragma unroll
    for (int i = 0; i < 4; i++) {
        int chunk = tid + 128*i;
        int r = chunk >> 3, c8 = chunk & 7;
        cpasync16(q_addr + (uint32_t)(r*ATS + c8*16),
                  qkv + (size_t)(qb*64 + r) * (3*DD) + c8*8);
    }
    load_kv(0, 0);

    // fragment lane offsets (same mappings as GEMM; ATS stride)
    uint32_t a_lane_off = (uint32_t)(((lsub & 1)*8 + lj)*ATS + (lsub >> 1)*16);
    uint32_t b_lane_off = (uint32_t)((((lsub >> 1)&1)*8 + lj)*ATS + (lsub & 1)*16);
    // V-trans frag: mats (k+lj,d),(k+8+lj,d),(k+lj,d+8),(k+8+lj,d+8)
    uint32_t vt_lane_off = (uint32_t)(((lsub & 1)*8 + lj)*ATS + (lsub >> 1)*16);

    float mrow[2] = {-3.0e38f, -3.0e38f};
    float lrow[2] = {0.f, 0.f};
    float accO[8][4];
#pragma unroll
    for (int ni = 0; ni < 8; ni++)
#pragma unroll
        for (int c = 0; c < 4; c++) accO[ni][c] = 0.f;

    int qrow = wid*16 + g;
    uint32_t q_tile = q_addr + (uint32_t)(wid*16*ATS) + a_lane_off;
    uint32_t p_tile = p_addr + (uint32_t)(wid*16*ATS) + a_lane_off;

    for (int jt = 0; jt <= qb; jt++) {
        if (jt < qb) load_kv((jt+1) & 1, jt+1);
        if (jt < qb) asm volatile("cp.async.wait_group 1;" ::: "memory");
        else         asm volatile("cp.async.wait_group 0;" ::: "memory");
        __syncthreads();

        uint32_t kbase = k_addr + (uint32_t)((jt & 1)*ATILE_B);
        uint32_t vbase = v_addr + (uint32_t)((jt & 1)*ATILE_B);

        // ---- S = Q @ K^T (bf16 mma16) ----
        float accS[8][4];
#pragma unroll
        for (int ni = 0; ni < 8; ni++)
#pragma unroll
            for (int c = 0; c < 4; c++) accS[ni][c] = 0.f;
#pragma unroll
        for (int ks = 0; ks < 4; ks++) {
            uint32_t kb = ks*32;
            uint32_t af[4];
            ldsm4(af[0], af[1], af[2], af[3], q_tile + kb);
#pragma unroll
            for (int p = 0; p < 4; p++) {
                uint32_t bf[2][2];
                ldsm4(bf[0][0], bf[0][1], bf[1][0], bf[1][1],
                      kbase + (uint32_t)(p*16*ATS) + b_lane_off + kb);
                mma16(accS[2*p],   af, bf[0]);
                mma16(accS[2*p+1], af, bf[1]);
            }
        }

        // ---- scale + causal mask (acc layout identical to mma8) ----
        bool diag = (jt == qb);
#pragma unroll
        for (int ni = 0; ni < 8; ni++)
#pragma unroll
            for (int c = 0; c < 4; c++) {
                float s = accS[ni][c] * 0.125f;
                if (diag) {
                    int kg = 8*ni + 2*tig + (c & 1);
                    int qg = wid*16 + g + 8*(c >> 1);
                    if (kg > qg) s = -3.0e38f;
                }
                accS[ni][c] = s;
            }

        // ---- online softmax ----
#pragma unroll
        for (int r = 0; r < 2; r++) {
            float rm = -3.0e38f;
#pragma unroll
            for (int ni = 0; ni < 8; ni++)
                rm = fmaxf(rm, fmaxf(accS[ni][2*r], accS[ni][2*r+1]));
            rm = fmaxf(rm, __shfl_xor_sync(0xffffffffu, rm, 1));
            rm = fmaxf(rm, __shfl_xor_sync(0xffffffffu, rm, 2));
            float mn = fmaxf(mrow[r], rm);
            float corr = __expf(mrow[r] - mn);
            mrow[r] = mn;
            float rs = 0.f;
#pragma unroll
            for (int ni = 0; ni < 8; ni++) {
                float p0 = __expf(accS[ni][2*r]   - mn);
                float p1 = __expf(accS[ni][2*r+1] - mn);
                rs += p0 + p1;
                accS[ni][2*r]   = p0;
                accS[ni][2*r+1] = p1;
            }
            rs += __shfl_xor_sync(0xffffffffu, rs, 1);
            rs += __shfl_xor_sync(0xffffffffu, rs, 2);
            lrow[r] = lrow[r] * corr + rs;
#pragma unroll
            for (int ni = 0; ni < 8; ni++) {
                accO[ni][2*r]   *= corr;
                accO[ni][2*r+1] *= corr;
            }
        }

        // ---- store P (bf16) to this warp's smem rows ----
#pragma unroll
        for (int ni = 0; ni < 8; ni++) {
            __nv_bfloat162 p0 = __floats2bfloat162_rn(accS[ni][0], accS[ni][1]);
            __nv_bfloat162 p1 = __floats2bfloat162_rn(accS[ni][2], accS[ni][3]);
            *(__nv_bfloat162*)(smA + (size_t)(p_addr - q_addr) + (qrow)*ATS + (8*ni + 2*tig)*2) = p0;
            *(__nv_bfloat162*)(smA + (size_t)(p_addr - q_addr) + (qrow+8)*ATS + (8*ni + 2*tig)*2) = p1;
        }
        __syncwarp();

        // ---- O += P @ V (bf16 mma16, V via ldsm.trans) ----
#pragma unroll
        for (int ks = 0; ks < 4; ks++) {
            uint32_t kb = ks*32;
            uint32_t af[4];
            ldsm4(af[0], af[1], af[2], af[3], p_tile + kb);
#pragma unroll
            for (int p = 0; p < 4; p++) {
                uint32_t bf[2][2];
                ldsm4t(bf[0][0], bf[0][1], bf[1][0], bf[1][1],
                       vbase + (uint32_t)(ks*16*ATS) + vt_lane_off + (uint32_t)(p*32));
                mma16(accO[2*p],   af, bf[0]);
                mma16(accO[2*p+1], af, bf[1]);
            }
        }
        __syncthreads();
    }

    // normalize + write bf16 (feeds o-proj GEMM)
    __nv_bfloat16* op = g_attn + (size_t)b * KK * DD + h * DHD;
#pragma unroll
    for (int r = 0; r < 2; r++) {
        float inv = 1.f / lrow[r];
        int row = qb*64 + wid*16 + g + 8*r;
#pragma unroll
        for (int ni = 0; ni < 8; ni++) {
            __nv_bfloat162 ov = __floats2bfloat162_rn(accO[ni][2*r]   * inv,
                                                      accO[ni][2*r+1] * inv);
            *(__nv_bfloat162*)(op + (size_t)row * DD + 8*ni + 2*tig) = ov;
        }
    }
}

// ---------------- launch ----------------
extern "C" void kernel_launch(void* const* d_in, const int* in_sizes, int n_in,
                              void* d_out, int out_size) {
    const float* x        = (const float*)d_in[0];
    const float* w_router = (const float*)d_in[1];
    const float* b_router = (const float*)d_in[2];
    const float* ln1_s    = (const float*)d_in[3];
    const float* ln1_b    = (const float*)d_in[4];
    const float* w_qkv    = (const float*)d_in[5];
    const float* b_qkv    = (const float*)d_in[6];
    const float* w_o      = (const float*)d_in[7];
    const float* b_o      = (const float*)d_in[8];
    const float* ln2_s    = (const float*)d_in[9];
    const float* ln2_b    = (const float*)d_in[10];
    const float* w1       = (const float*)d_in[11];
    const float* b1       = (const float*)d_in[12];
    const float* w2       = (const float*)d_in[13];
    const float* b2       = (const float*)d_in[14];
    float* out = (float*)d_out;

    float *p_h;
    __nv_bfloat16 *p_a, *p_qkv, *p_attn, *p_ffn, *p_wt;
    cudaGetSymbolAddress((void**)&p_h,    g_h);
    cudaGetSymbolAddress((void**)&p_a,    g_a);
    cudaGetSymbolAddress((void**)&p_qkv,  g_qkv);
    cudaGetSymbolAddress((void**)&p_attn, g_attn);
    cudaGetSymbolAddress((void**)&p_ffn,  g_ffn);
    cudaGetSymbolAddress((void**)&p_wt,   g_wt);

    cudaFuncSetAttribute(attn_mma_kernel, cudaFuncAttributeMaxDynamicSharedMemorySize,
                         ATTN3_SMEM);
    cudaFuncSetAttribute(mma_gemm<1>, cudaFuncAttributeMaxDynamicSharedMemorySize, GEMM_SMEM);
    cudaFuncSetAttribute(mma_gemm<2>, cudaFuncAttributeMaxDynamicSharedMemorySize, GEMM_SMEM);
    cudaFuncSetAttribute(mma_gemm<4>, cudaFuncAttributeMaxDynamicSharedMemorySize, GEMM_SMEM);

    // 1: weight transpose + bf16 round + router (fused)
    trans_router_kernel<<<TRT_TILES + BB*TT/8, 256>>>(
        x, w_router, b_router, w_qkv, w_o, w1, w2);
    // 2: exact top-K
    topk_kernel<<<BB, 1024>>>();
    // 3: gather + layer-0 ln1
    gather_ln_kernel<<<MROWS, 256>>>(x, ln1_s, ln1_b);

    for (int l = 0; l < LL; l++) {
        if (l > 0)
            ln_kernel<<<MROWS, 256>>>(p_h, ln1_s + l*DD, ln1_b + l*DD, p_a);
        // 4 (for l=0): qkv GEMM -> profiled launch (bf16 out)
        mma_gemm<4><<<dim3(3*DD/NTB, MROWS/MT), GEMM_THREADS, GEMM_SMEM>>>(
            p_a, p_wt + WT_QKV + (size_t)l*3*DD*DD, b_qkv + (size_t)l*3*DD, nullptr,
            (float*)p_qkv, DD, 3*DD);
        attn_mma_kernel<<<dim3(KK/64, BB*HH), 128, ATTN3_SMEM>>>();
        mma_gemm<2><<<dim3(DD/NTB, MROWS/MT), GEMM_THREADS, GEMM_SMEM>>>(
            p_attn, p_wt + WT_O + (size_t)l*DD*DD, b_o + (size_t)l*DD, p_h,
            p_h, DD, DD);
        ln_kernel<<<MROWS, 256>>>(p_h, ln2_s + l*DD, ln2_b + l*DD, p_a);
        mma_gemm<1><<<dim3(FF/NTB, MROWS/MT), GEMM_THREADS, GEMM_SMEM>>>(
            p_a, p_wt + WT_W1 + (size_t)l*FF*DD, b1 + (size_t)l*FF, nullptr,
            (float*)p_ffn, DD, FF);
        mma_gemm<2><<<dim3(DD/NTB, MROWS/MT), GEMM_THREADS, GEMM_SMEM>>>(
            p_ffn, p_wt + WT_W2 + (size_t)l*DD*FF, b2 + (size_t)l*DD, p_h,
            p_h, FF, DD);
    }

    long long full = (long long)BB*TT*DD + (long long)BB*KK + (long long)BB*TT;
    int tail_blocks = ((long long)out_size >= full) ? 32 : 0;
    out_kernel<<<OUT_MAIN_BLOCKS + tail_blocks, 256>>>(x, out);
}